// round 10
// baseline (speedup 1.0000x reference)
#include <cuda_runtime.h>
#include <cuda_bf16.h>

#define B_DIM 4
#define S_DIM 4096
#define F_DIM 512
#define D_DIM 64
#define EGRID 608
#define TOTAL_JOBS 16384   // 256 i-blocks(64) x 64 j-tiles(64)

// ---------------- scratch (no cudaMalloc allowed) ----------------
__device__ __nv_bfloat16 g_Qhi[B_DIM * S_DIM * D_DIM];
__device__ __nv_bfloat16 g_Qlo[B_DIM * S_DIM * D_DIM];
__device__ __nv_bfloat16 g_Khi[B_DIM * S_DIM * D_DIM];
__device__ __nv_bfloat16 g_Klo[B_DIM * S_DIM * D_DIM];
__device__ unsigned char g_Whs[8 * 16384];   // pre-swizzled W hi tiles
__device__ unsigned char g_Wls[8 * 16384];   // pre-swizzled W lo tiles
__device__ float2 g_rcp[8192];               // (1/max(|k-4096|,1), 1/max(|k-4097|,1))

typedef unsigned long long u64;
typedef unsigned u32;

__device__ __forceinline__ float fast_rcp(float x) {
    float r; asm("rcp.approx.f32 %0, %1;" : "=f"(r) : "f"(x)); return r;
}
__device__ __forceinline__ u32 smem_u32(const void* p) {
    u32 a;
    asm("{ .reg .u64 t; cvta.to.shared.u64 t, %1; cvt.u32.u64 %0, t; }" : "=r"(a) : "l"(p));
    return a;
}
__device__ __forceinline__ void ldsm_x4(u32& r0, u32& r1, u32& r2, u32& r3, u32 addr) {
    asm volatile("ldmatrix.sync.aligned.m8n8.x4.shared.b16 {%0,%1,%2,%3}, [%4];"
                 : "=r"(r0), "=r"(r1), "=r"(r2), "=r"(r3) : "r"(addr));
}
__device__ __forceinline__ void mma16816(float* c, const u32* a, const u32* b) {
    asm volatile(
        "mma.sync.aligned.m16n8k16.row.col.f32.bf16.bf16.f32 "
        "{%0,%1,%2,%3}, {%4,%5,%6,%7}, {%8,%9}, {%0,%1,%2,%3};"
        : "+f"(c[0]), "+f"(c[1]), "+f"(c[2]), "+f"(c[3])
        : "r"(a[0]), "r"(a[1]), "r"(a[2]), "r"(a[3]), "r"(b[0]), "r"(b[1]));
}
__device__ __forceinline__ void cp16(u32 dst, const void* src) {
    asm volatile("cp.async.cg.shared.global [%0], [%1], 16;" :: "r"(dst), "l"(src));
}
__device__ __forceinline__ void cp_commit() { asm volatile("cp.async.commit_group;" ::: "memory"); }
__device__ __forceinline__ void cp_wait0()  { asm volatile("cp.async.wait_group 0;" ::: "memory"); }
__device__ __forceinline__ void cp_wait1()  { asm volatile("cp.async.wait_group 1;" ::: "memory"); }

__device__ __forceinline__ void split2(float x, float y, u32& h, u32& l) {
    __nv_bfloat162 hh = __floats2bfloat162_rn(x, y);
    float rx = x - __bfloat162float(hh.x);
    float ry = y - __bfloat162float(hh.y);
    __nv_bfloat162 ll = __floats2bfloat162_rn(rx, ry);
    h = *(u32*)&hh; l = *(u32*)&ll;
}

// =================================================================
// W setup: split Wq|Wk to bf16 hi/lo pre-swizzled tile images
// + build reciprocal-distance table (8192 threads = 8192 entries)
// =================================================================
__global__ __launch_bounds__(256) void wsetup_kernel(
    const float* __restrict__ Wq, const float* __restrict__ Wk)
{
    int idx = blockIdx.x * 256 + threadIdx.x;   // 8192 items
    // reciprocal-distance table entry
    {
        float d0 = fmaxf(fabsf((float)(idx - 4096)), 1.f);
        float d1 = fmaxf(fabsf((float)(idx - 4097)), 1.f);
        float2 r;
        r.x = fast_rcp(d0);
        r.y = fast_rcp(d1);
        g_rcp[idx] = r;
    }
    int c = idx >> 10;
    int j = (idx >> 3) & 127;
    int a = idx & 7;
    const float* wp = (j < 64) ? (Wq + j) : (Wk + (j - 64));
    int f0 = c * 64 + a * 8;
    float wv[8];
    #pragma unroll
    for (int k = 0; k < 8; ++k) wv[k] = wp[(size_t)(f0 + k) * D_DIM];
    uint4 H, L;
    split2(wv[0], wv[1], H.x, L.x);
    split2(wv[2], wv[3], H.y, L.y);
    split2(wv[4], wv[5], H.z, L.z);
    split2(wv[6], wv[7], H.w, L.w);
    u32 off = (u32)j * 128 + (u32)a * 16;
    u32 swo = off ^ ((off >> 3) & 0x70);
    *(uint4*)(g_Whs + c * 16384 + swo) = H;
    *(uint4*)(g_Wls + c * 16384 + swo) = L;
}

// =================================================================
// proj: 64-row tiles, grid 256, 2 CTAs/SM. HMMA [64] x [128 = Q|K].
// (identical to R8 — best-known)
// =================================================================
#define P_FHI 0
#define P_FLO 8192
#define P_W   16384
#define P_WCS 81920
#define P_CHR 82432
#define P_SMEM 82944

__global__ __launch_bounds__(256, 2) void proj_kernel(
    const float* __restrict__ feat, const float* __restrict__ wch,
    const float* __restrict__ bch, const float* __restrict__ loc_p)
{
    extern __shared__ char smem[];
    const u32 sb = smem_u32(smem);
    float* wcs   = (float*)(smem + P_WCS);
    float* chRow = (float*)(smem + P_CHR);

    const int t = threadIdx.x;
    const int wid = t >> 5, lid = t & 31;
    const int wm = wid & 1, wn = wid >> 1;
    const int rowBase = blockIdx.x * 64;

    const int fr = t >> 2, ffo = (t & 3) * 16;
    const int watom = t * 16;

    if (t < 64) wcs[t] = wch[t];

    const u32 lxor  = ((u32)(lid & 7)) << 4;
    const u32 abase = (u32)((wm * 32) + (lid & 7) + ((lid >> 3) & 1) * 8) * 128;
    const u32 ach   = ((u32)(lid >> 4) & 1) * 16;
    const u32 bbase4 = (u32)((wn * 32) + ((lid >> 4) & 1) * 8 + (lid & 7)) * 128;
    const u32 bk4    = ((u32)(lid >> 3) & 1) * 16;

    float acc[2][4][4] = {};
    float csum = 0.f;

    {
        u32 wb = sb + P_W;
        #pragma unroll
        for (int a = 0; a < 4; ++a) {
            cp16(wb + watom + a * 4096, g_Whs + watom + a * 4096);
            cp16(wb + 16384 + watom + a * 4096, g_Wls + watom + a * 4096);
        }
        cp_commit();
    }

    for (int c = 0; c < 8; ++c) {
        const int f0 = c * 64;
        const u32 wb = sb + P_W + (c & 1) * 32768;
        __syncthreads();
        const float* wc_cur = wcs + (c & 1) * 64;
        {
            const float* fp = feat + (size_t)(rowBase + fr) * F_DIM + f0 + ffo;
            #pragma unroll
            for (int a = 0; a < 2; ++a) {
                float4 v0 = *(const float4*)(fp + a * 8);
                float4 v1 = *(const float4*)(fp + a * 8 + 4);
                csum += v0.x * wc_cur[ffo + a*8 + 0] + v0.y * wc_cur[ffo + a*8 + 1]
                      + v0.z * wc_cur[ffo + a*8 + 2] + v0.w * wc_cur[ffo + a*8 + 3]
                      + v1.x * wc_cur[ffo + a*8 + 4] + v1.y * wc_cur[ffo + a*8 + 5]
                      + v1.z * wc_cur[ffo + a*8 + 6] + v1.w * wc_cur[ffo + a*8 + 7];
                uint4 H, L;
                split2(v0.x, v0.y, H.x, L.x);
                split2(v0.z, v0.w, H.y, L.y);
                split2(v1.x, v1.y, H.z, L.z);
                split2(v1.z, v1.w, H.w, L.w);
                u32 off = (u32)fr * 128 + (u32)(ffo + a * 8) * 2;
                u32 swo = off ^ ((off >> 3) & 0x70);
                *(uint4*)(smem + P_FHI + swo) = H;
                *(uint4*)(smem + P_FLO + swo) = L;
            }
        }
        if (c + 1 < 8) {
            u32 nwb = sb + P_W + ((c + 1) & 1) * 32768;
            const unsigned char* gh = g_Whs + (c + 1) * 16384;
            const unsigned char* gl = g_Wls + (c + 1) * 16384;
            #pragma unroll
            for (int a = 0; a < 4; ++a) {
                cp16(nwb + watom + a * 4096, gh + watom + a * 4096);
                cp16(nwb + 16384 + watom + a * 4096, gl + watom + a * 4096);
            }
            cp_commit();
            cp_wait1();
        } else {
            cp_wait0();
        }
        if (t < 64 && c + 1 < 8) wcs[((c + 1) & 1) * 64 + t] = wch[f0 + 64 + t];
        __syncthreads();

        #pragma unroll
        for (int ks = 0; ks < 4; ++ks) {
            const u32 akb = ((u32)(ks * 32) + ach) ^ lxor;
            const u32 bkb = ((u32)(ks * 32) + bk4) ^ lxor;
            u32 afH[2][4], afL[2][4], bH[8], bL[8];
            #pragma unroll
            for (int mt = 0; mt < 2; ++mt)
                ldsm_x4(afH[mt][0], afH[mt][1], afH[mt][2], afH[mt][3],
                        sb + P_FHI + abase + mt * 2048 + akb);
            ldsm_x4(bH[0], bH[1], bH[2], bH[3], wb + bbase4 + bkb);
            ldsm_x4(bH[4], bH[5], bH[6], bH[7], wb + bbase4 + 2048 + bkb);
            #pragma unroll
            for (int mt = 0; mt < 2; ++mt)
                #pragma unroll
                for (int nt = 0; nt < 4; ++nt)
                    mma16816(acc[mt][nt], afH[mt], bH + nt * 2);
            ldsm_x4(bL[0], bL[1], bL[2], bL[3], wb + 16384 + bbase4 + bkb);
            ldsm_x4(bL[4], bL[5], bL[6], bL[7], wb + 16384 + bbase4 + 2048 + bkb);
            #pragma unroll
            for (int mt = 0; mt < 2; ++mt)
                #pragma unroll
                for (int nt = 0; nt < 4; ++nt)
                    mma16816(acc[mt][nt], afH[mt], bL + nt * 2);
            #pragma unroll
            for (int mt = 0; mt < 2; ++mt)
                ldsm_x4(afL[mt][0], afL[mt][1], afL[mt][2], afL[mt][3],
                        sb + P_FLO + abase + mt * 2048 + akb);
            #pragma unroll
            for (int mt = 0; mt < 2; ++mt)
                #pragma unroll
                for (int nt = 0; nt < 4; ++nt)
                    mma16816(acc[mt][nt], afL[mt], bH + nt * 2);
        }
    }

    csum += __shfl_xor_sync(0xffffffffu, csum, 1);
    csum += __shfl_xor_sync(0xffffffffu, csum, 2);
    if ((t & 3) == 0) chRow[fr] = 1.f / (1.f + expf(-(csum + bch[0])));
    __syncthreads();

    const float nls = -0.125f * loc_p[0];
    const int g = lid >> 2, tg = lid & 3;
    #pragma unroll
    for (int mt = 0; mt < 2; ++mt) {
        #pragma unroll
        for (int half = 0; half < 2; ++half) {
            int il = wm * 32 + mt * 16 + g + half * 8;
            size_t row = (size_t)(rowBase + il);
            float cr = chRow[il];
            #pragma unroll
            for (int nt = 0; nt < 4; ++nt) {
                int jl = wn * 32 + nt * 8 + tg * 2;
                float sc = (jl < 64) ? (nls * cr) : cr;
                float c0 = acc[mt][nt][half * 2 + 0] * sc;
                float c1 = acc[mt][nt][half * 2 + 1] * sc;
                u32 h, l;
                split2(c0, c1, h, l);
                if (jl < 64) {
                    *(u32*)&g_Qhi[row * D_DIM + jl] = h;
                    *(u32*)&g_Qlo[row * D_DIM + jl] = l;
                } else {
                    *(u32*)&g_Khi[row * D_DIM + jl - 64] = h;
                    *(u32*)&g_Klo[row * D_DIM + jl - 64] = l;
                }
            }
        }
    }
}

// =================================================================
// energy: persistent, 4 CTAs/SM (128 threads), job tile 64(i) x 64(j)
// A-hi fragments hoisted per i-block; B via x4 LDSM; K double-buffered
// cp.async; epilogue uses precomputed reciprocal-distance table.
// smem: Qhi 0(8K), Qlo 8K, Kbuf0 {hi 16K, lo 24K}, Kbuf1 {hi 32K, lo 40K}
// =================================================================
#define E_Q 0
#define E_K 16384
#define E_SMEM 49152

__global__ __launch_bounds__(128, 4) void energy_kernel(float* __restrict__ out)
{
    extern __shared__ char smem[];
    const u32 sb = smem_u32(smem);

    const int t = threadIdx.x;
    const int wid = t >> 5, lid = t & 31;
    const int wm = wid & 1, wn = wid >> 1;

    const int js = (int)(((long long)blockIdx.x * TOTAL_JOBS) / EGRID);
    const int je = (int)(((long long)(blockIdx.x + 1) * TOTAL_JOBS) / EGRID);

    const int lc16 = t & 7;
    const int row16 = t >> 3;     // + 16*l

    const u32 lxor  = ((u32)(lid & 7)) << 4;
    const u32 abase = (u32)((wm * 32) + (lid & 7) + ((lid >> 3) & 1) * 8) * 128;
    const u32 ach   = ((u32)(lid >> 4) & 1) * 16;
    const u32 bbase4 = (u32)((wn * 32) + ((lid >> 4) & 1) * 8 + (lid & 7)) * 128;
    const u32 bk4    = ((u32)(lid >> 3) & 1) * 16;

    // prefetch K for first job
    {
        int job = js;
        int ib = job >> 6;
        size_t krow0 = (size_t)(ib >> 6) * S_DIM + (size_t)(job & 63) * 64;
        u32 kb = sb + E_K;
        #pragma unroll
        for (int l = 0; l < 4; ++l) {
            int row = row16 + 16 * l;
            u32 off = (u32)row * 128 + (u32)lc16 * 16;
            u32 swo = off ^ ((off >> 3) & 0x70);
            cp16(kb + swo, (const char*)(g_Khi + (krow0 + row) * D_DIM) + lc16 * 16);
            cp16(kb + 8192 + swo, (const char*)(g_Klo + (krow0 + row) * D_DIM) + lc16 * 16);
        }
        cp_commit();
    }

    int curIb = -1;
    u32 afH[4][2][4];   // hoisted A-hi fragments: [ks][mt][4]

    for (int job = js; job < je; ++job) {
        const int ib = job >> 6;
        const int jt = job & 63;
        const int buf = (job - js) & 1;
        const u32 kb = sb + E_K + buf * 16384;

        cp_wait0();
        __syncthreads();

        if (ib != curIb) {
            size_t qrow0 = (size_t)ib * 64;
            #pragma unroll
            for (int l = 0; l < 4; ++l) {
                int row = row16 + 16 * l;
                u32 off = (u32)row * 128 + (u32)lc16 * 16;
                u32 swo = off ^ ((off >> 3) & 0x70);
                *(uint4*)(smem + E_Q + swo) =
                    *(const uint4*)((const char*)(g_Qhi + (qrow0 + row) * D_DIM) + lc16 * 16);
                *(uint4*)(smem + E_Q + 8192 + swo) =
                    *(const uint4*)((const char*)(g_Qlo + (qrow0 + row) * D_DIM) + lc16 * 16);
            }
            curIb = ib;
            __syncthreads();
            #pragma unroll
            for (int ks = 0; ks < 4; ++ks) {
                const u32 akb = ((u32)(ks * 32) + ach) ^ lxor;
                #pragma unroll
                for (int mt = 0; mt < 2; ++mt)
                    ldsm_x4(afH[ks][mt][0], afH[ks][mt][1], afH[ks][mt][2], afH[ks][mt][3],
                            sb + E_Q + abase + mt * 2048 + akb);
            }
        }

        // prefetch next K (overlaps MMA)
        if (job + 1 < je) {
            int nj = job + 1;
            int nib = nj >> 6;
            size_t krow0 = (size_t)(nib >> 6) * S_DIM + (size_t)(nj & 63) * 64;
            u32 nkb = sb + E_K + (buf ^ 1) * 16384;
            #pragma unroll
            for (int l = 0; l < 4; ++l) {
                int row = row16 + 16 * l;
                u32 off = (u32)row * 128 + (u32)lc16 * 16;
                u32 swo = off ^ ((off >> 3) & 0x70);
                cp16(nkb + swo, (const char*)(g_Khi + (krow0 + row) * D_DIM) + lc16 * 16);
                cp16(nkb + 8192 + swo, (const char*)(g_Klo + (krow0 + row) * D_DIM) + lc16 * 16);
            }
            cp_commit();
        }

        // ---- fused 3-pass MMA: afH hoisted, B via x4, aL per job ----
        float acc[2][4][4] = {};
        #pragma unroll
        for (int ks = 0; ks < 4; ++ks) {
            const u32 akb = ((u32)(ks * 32) + ach) ^ lxor;
            const u32 bkb = ((u32)(ks * 32) + bk4) ^ lxor;
            u32 bH[8], bL[8], aL[2][4];
            ldsm_x4(bH[0], bH[1], bH[2], bH[3], kb + bbase4 + bkb);
            ldsm_x4(bH[4], bH[5], bH[6], bH[7], kb + bbase4 + 2048 + bkb);
            #pragma unroll
            for (int mt = 0; mt < 2; ++mt)
                #pragma unroll
                for (int nt = 0; nt < 4; ++nt)
                    mma16816(acc[mt][nt], afH[ks][mt], bH + nt * 2);
            ldsm_x4(bL[0], bL[1], bL[2], bL[3], kb + 8192 + bbase4 + bkb);
            ldsm_x4(bL[4], bL[5], bL[6], bL[7], kb + 8192 + bbase4 + 2048 + bkb);
            #pragma unroll
            for (int mt = 0; mt < 2; ++mt)
                #pragma unroll
                for (int nt = 0; nt < 4; ++nt)
                    mma16816(acc[mt][nt], afH[ks][mt], bL + nt * 2);
            #pragma unroll
            for (int mt = 0; mt < 2; ++mt)
                ldsm_x4(aL[mt][0], aL[mt][1], aL[mt][2], aL[mt][3],
                        sb + E_Q + 8192 + abase + mt * 2048 + akb);
            #pragma unroll
            for (int mt = 0; mt < 2; ++mt)
                #pragma unroll
                for (int nt = 0; nt < 4; ++nt)
                    mma16816(acc[mt][nt], aL[mt], bH + nt * 2);
        }

        // ---- epilogue: v * table-rcp(|i-j|) ----
        const int iPos0 = (ib & 63) * 64;
        const int jj0 = jt * 64;
        const int g = lid >> 2, tg = lid & 3;
        float* ob = out + ((size_t)ib * 64) * S_DIM + jj0;
        #pragma unroll
        for (int mt = 0; mt < 2; ++mt) {
            #pragma unroll
            for (int half = 0; half < 2; ++half) {
                int il = wm * 32 + mt * 16 + g + half * 8;
                // table index for jl=0: 4096 + (ip - jj0)
                int kbase = 4096 + iPos0 + il - jj0;
                float* orow = ob + (size_t)il * S_DIM;
                #pragma unroll
                for (int nt = 0; nt < 4; ++nt) {
                    int jl = wn * 32 + nt * 8 + tg * 2;
                    float2 r = g_rcp[kbase - jl];
                    float2 o;
                    o.x = acc[mt][nt][half * 2 + 0] * r.x;
                    o.y = acc[mt][nt][half * 2 + 1] * r.y;
                    *(float2*)(orow + jl) = o;
                }
            }
        }
    }
}

extern "C" void kernel_launch(void* const* d_in, const int* in_sizes, int n_in,
                              void* d_out, int out_size) {
    const float* feat = (const float*)d_in[0];
    const float* Wq   = (const float*)d_in[1];
    const float* Wk   = (const float*)d_in[2];
    const float* wch  = (const float*)d_in[3];
    const float* bch  = (const float*)d_in[4];
    const float* ls   = (const float*)d_in[5];
    float* out = (float*)d_out;

    cudaFuncSetAttribute(proj_kernel, cudaFuncAttributeMaxDynamicSharedMemorySize, P_SMEM);
    cudaFuncSetAttribute(energy_kernel, cudaFuncAttributeMaxDynamicSharedMemorySize, E_SMEM);

    wsetup_kernel<<<32, 256>>>(Wq, Wk);
    proj_kernel<<<(B_DIM * S_DIM) / 64, 256, P_SMEM>>>(feat, wch, bch, ls);
    energy_kernel<<<EGRID, 128, E_SMEM>>>(out);
}

// round 11
// speedup vs baseline: 1.0856x; 1.0856x over previous
#include <cuda_runtime.h>
#include <cuda_bf16.h>

#define B_DIM 4
#define S_DIM 4096
#define F_DIM 512
#define D_DIM 64
#define EGRID 608
#define TOTAL_JOBS 16384   // 256 i-blocks(64) x 64 j-tiles(64)

// ---------------- scratch (no cudaMalloc allowed) ----------------
__device__ __nv_bfloat16 g_Qhi[B_DIM * S_DIM * D_DIM];
__device__ __nv_bfloat16 g_Qlo[B_DIM * S_DIM * D_DIM];
__device__ __nv_bfloat16 g_Khi[B_DIM * S_DIM * D_DIM];
__device__ __nv_bfloat16 g_Klo[B_DIM * S_DIM * D_DIM];
__device__ unsigned char g_Whs[8 * 16384];   // pre-swizzled W hi tiles
__device__ unsigned char g_Wls[8 * 16384];   // pre-swizzled W lo tiles

typedef unsigned long long u64;
typedef unsigned u32;

__device__ __forceinline__ float fast_rcp(float x) {
    float r; asm("rcp.approx.f32 %0, %1;" : "=f"(r) : "f"(x)); return r;
}
__device__ __forceinline__ u32 smem_u32(const void* p) {
    u32 a;
    asm("{ .reg .u64 t; cvta.to.shared.u64 t, %1; cvt.u32.u64 %0, t; }" : "=r"(a) : "l"(p));
    return a;
}
__device__ __forceinline__ void ldsm_x4(u32& r0, u32& r1, u32& r2, u32& r3, u32 addr) {
    asm volatile("ldmatrix.sync.aligned.m8n8.x4.shared.b16 {%0,%1,%2,%3}, [%4];"
                 : "=r"(r0), "=r"(r1), "=r"(r2), "=r"(r3) : "r"(addr));
}
__device__ __forceinline__ void mma16816(float* c, const u32* a, const u32* b) {
    asm volatile(
        "mma.sync.aligned.m16n8k16.row.col.f32.bf16.bf16.f32 "
        "{%0,%1,%2,%3}, {%4,%5,%6,%7}, {%8,%9}, {%0,%1,%2,%3};"
        : "+f"(c[0]), "+f"(c[1]), "+f"(c[2]), "+f"(c[3])
        : "r"(a[0]), "r"(a[1]), "r"(a[2]), "r"(a[3]), "r"(b[0]), "r"(b[1]));
}
__device__ __forceinline__ void cp16(u32 dst, const void* src) {
    asm volatile("cp.async.cg.shared.global [%0], [%1], 16;" :: "r"(dst), "l"(src));
}
__device__ __forceinline__ void cp_commit() { asm volatile("cp.async.commit_group;" ::: "memory"); }
__device__ __forceinline__ void cp_wait0()  { asm volatile("cp.async.wait_group 0;" ::: "memory"); }
__device__ __forceinline__ void cp_wait1()  { asm volatile("cp.async.wait_group 1;" ::: "memory"); }

__device__ __forceinline__ void split2(float x, float y, u32& h, u32& l) {
    __nv_bfloat162 hh = __floats2bfloat162_rn(x, y);
    float rx = x - __bfloat162float(hh.x);
    float ry = y - __bfloat162float(hh.y);
    __nv_bfloat162 ll = __floats2bfloat162_rn(rx, ry);
    h = *(u32*)&hh; l = *(u32*)&ll;
}

// =================================================================
// W setup: split Wq|Wk to bf16 hi/lo pre-swizzled tile images
// =================================================================
__global__ __launch_bounds__(256) void wsetup_kernel(
    const float* __restrict__ Wq, const float* __restrict__ Wk)
{
    int idx = blockIdx.x * 256 + threadIdx.x;   // 8192 items
    int c = idx >> 10;
    int j = (idx >> 3) & 127;
    int a = idx & 7;
    const float* wp = (j < 64) ? (Wq + j) : (Wk + (j - 64));
    int f0 = c * 64 + a * 8;
    float wv[8];
    #pragma unroll
    for (int k = 0; k < 8; ++k) wv[k] = wp[(size_t)(f0 + k) * D_DIM];
    uint4 H, L;
    split2(wv[0], wv[1], H.x, L.x);
    split2(wv[2], wv[3], H.y, L.y);
    split2(wv[4], wv[5], H.z, L.z);
    split2(wv[6], wv[7], H.w, L.w);
    u32 off = (u32)j * 128 + (u32)a * 16;
    u32 swo = off ^ ((off >> 3) & 0x70);
    *(uint4*)(g_Whs + c * 16384 + swo) = H;
    *(uint4*)(g_Wls + c * 16384 + swo) = L;
}

// =================================================================
// proj: 64-row tiles, grid 256, 2 CTAs/SM. HMMA [64] x [128 = Q|K].
// (identical to R8 — best-known)
// =================================================================
#define P_FHI 0
#define P_FLO 8192
#define P_W   16384
#define P_WCS 81920
#define P_CHR 82432
#define P_SMEM 82944

__global__ __launch_bounds__(256, 2) void proj_kernel(
    const float* __restrict__ feat, const float* __restrict__ wch,
    const float* __restrict__ bch, const float* __restrict__ loc_p)
{
    extern __shared__ char smem[];
    const u32 sb = smem_u32(smem);
    float* wcs   = (float*)(smem + P_WCS);
    float* chRow = (float*)(smem + P_CHR);

    const int t = threadIdx.x;
    const int wid = t >> 5, lid = t & 31;
    const int wm = wid & 1, wn = wid >> 1;
    const int rowBase = blockIdx.x * 64;

    const int fr = t >> 2, ffo = (t & 3) * 16;
    const int watom = t * 16;

    if (t < 64) wcs[t] = wch[t];

    const u32 lxor  = ((u32)(lid & 7)) << 4;
    const u32 abase = (u32)((wm * 32) + (lid & 7) + ((lid >> 3) & 1) * 8) * 128;
    const u32 ach   = ((u32)(lid >> 4) & 1) * 16;
    const u32 bbase4 = (u32)((wn * 32) + ((lid >> 4) & 1) * 8 + (lid & 7)) * 128;
    const u32 bk4    = ((u32)(lid >> 3) & 1) * 16;

    float acc[2][4][4] = {};
    float csum = 0.f;

    {
        u32 wb = sb + P_W;
        #pragma unroll
        for (int a = 0; a < 4; ++a) {
            cp16(wb + watom + a * 4096, g_Whs + watom + a * 4096);
            cp16(wb + 16384 + watom + a * 4096, g_Wls + watom + a * 4096);
        }
        cp_commit();
    }

    for (int c = 0; c < 8; ++c) {
        const int f0 = c * 64;
        const u32 wb = sb + P_W + (c & 1) * 32768;
        __syncthreads();
        const float* wc_cur = wcs + (c & 1) * 64;
        {
            const float* fp = feat + (size_t)(rowBase + fr) * F_DIM + f0 + ffo;
            #pragma unroll
            for (int a = 0; a < 2; ++a) {
                float4 v0 = *(const float4*)(fp + a * 8);
                float4 v1 = *(const float4*)(fp + a * 8 + 4);
                csum += v0.x * wc_cur[ffo + a*8 + 0] + v0.y * wc_cur[ffo + a*8 + 1]
                      + v0.z * wc_cur[ffo + a*8 + 2] + v0.w * wc_cur[ffo + a*8 + 3]
                      + v1.x * wc_cur[ffo + a*8 + 4] + v1.y * wc_cur[ffo + a*8 + 5]
                      + v1.z * wc_cur[ffo + a*8 + 6] + v1.w * wc_cur[ffo + a*8 + 7];
                uint4 H, L;
                split2(v0.x, v0.y, H.x, L.x);
                split2(v0.z, v0.w, H.y, L.y);
                split2(v1.x, v1.y, H.z, L.z);
                split2(v1.z, v1.w, H.w, L.w);
                u32 off = (u32)fr * 128 + (u32)(ffo + a * 8) * 2;
                u32 swo = off ^ ((off >> 3) & 0x70);
                *(uint4*)(smem + P_FHI + swo) = H;
                *(uint4*)(smem + P_FLO + swo) = L;
            }
        }
        if (c + 1 < 8) {
            u32 nwb = sb + P_W + ((c + 1) & 1) * 32768;
            const unsigned char* gh = g_Whs + (c + 1) * 16384;
            const unsigned char* gl = g_Wls + (c + 1) * 16384;
            #pragma unroll
            for (int a = 0; a < 4; ++a) {
                cp16(nwb + watom + a * 4096, gh + watom + a * 4096);
                cp16(nwb + 16384 + watom + a * 4096, gl + watom + a * 4096);
            }
            cp_commit();
            cp_wait1();
        } else {
            cp_wait0();
        }
        if (t < 64 && c + 1 < 8) wcs[((c + 1) & 1) * 64 + t] = wch[f0 + 64 + t];
        __syncthreads();

        #pragma unroll
        for (int ks = 0; ks < 4; ++ks) {
            const u32 akb = ((u32)(ks * 32) + ach) ^ lxor;
            const u32 bkb = ((u32)(ks * 32) + bk4) ^ lxor;
            u32 afH[2][4], afL[2][4], bH[8], bL[8];
            #pragma unroll
            for (int mt = 0; mt < 2; ++mt)
                ldsm_x4(afH[mt][0], afH[mt][1], afH[mt][2], afH[mt][3],
                        sb + P_FHI + abase + mt * 2048 + akb);
            ldsm_x4(bH[0], bH[1], bH[2], bH[3], wb + bbase4 + bkb);
            ldsm_x4(bH[4], bH[5], bH[6], bH[7], wb + bbase4 + 2048 + bkb);
            #pragma unroll
            for (int mt = 0; mt < 2; ++mt)
                #pragma unroll
                for (int nt = 0; nt < 4; ++nt)
                    mma16816(acc[mt][nt], afH[mt], bH + nt * 2);
            ldsm_x4(bL[0], bL[1], bL[2], bL[3], wb + 16384 + bbase4 + bkb);
            ldsm_x4(bL[4], bL[5], bL[6], bL[7], wb + 16384 + bbase4 + 2048 + bkb);
            #pragma unroll
            for (int mt = 0; mt < 2; ++mt)
                #pragma unroll
                for (int nt = 0; nt < 4; ++nt)
                    mma16816(acc[mt][nt], afH[mt], bL + nt * 2);
            #pragma unroll
            for (int mt = 0; mt < 2; ++mt)
                ldsm_x4(afL[mt][0], afL[mt][1], afL[mt][2], afL[mt][3],
                        sb + P_FLO + abase + mt * 2048 + akb);
            #pragma unroll
            for (int mt = 0; mt < 2; ++mt)
                #pragma unroll
                for (int nt = 0; nt < 4; ++nt)
                    mma16816(acc[mt][nt], afL[mt], bH + nt * 2);
        }
    }

    csum += __shfl_xor_sync(0xffffffffu, csum, 1);
    csum += __shfl_xor_sync(0xffffffffu, csum, 2);
    if ((t & 3) == 0) chRow[fr] = 1.f / (1.f + expf(-(csum + bch[0])));
    __syncthreads();

    const float nls = -0.125f * loc_p[0];
    const int g = lid >> 2, tg = lid & 3;
    #pragma unroll
    for (int mt = 0; mt < 2; ++mt) {
        #pragma unroll
        for (int half = 0; half < 2; ++half) {
            int il = wm * 32 + mt * 16 + g + half * 8;
            size_t row = (size_t)(rowBase + il);
            float cr = chRow[il];
            #pragma unroll
            for (int nt = 0; nt < 4; ++nt) {
                int jl = wn * 32 + nt * 8 + tg * 2;
                float sc = (jl < 64) ? (nls * cr) : cr;
                float c0 = acc[mt][nt][half * 2 + 0] * sc;
                float c1 = acc[mt][nt][half * 2 + 1] * sc;
                u32 h, l;
                split2(c0, c1, h, l);
                if (jl < 64) {
                    *(u32*)&g_Qhi[row * D_DIM + jl] = h;
                    *(u32*)&g_Qlo[row * D_DIM + jl] = l;
                } else {
                    *(u32*)&g_Khi[row * D_DIM + jl - 64] = h;
                    *(u32*)&g_Klo[row * D_DIM + jl - 64] = l;
                }
            }
        }
    }
}

// =================================================================
// energy: persistent, 4 CTAs/SM (128 threads), job tile 64(i) x 64(j)
// A-hi fragments hoisted; B via x4 LDSM; K double-buffered cp.async;
// epilogue: shuffle-packed STG.128 (halves store wavefronts).
// smem: Qhi 0(8K), Qlo 8K, Kbuf0 {hi 16K, lo 24K}, Kbuf1 {hi 32K, lo 40K}
// =================================================================
#define E_Q 0
#define E_K 16384
#define E_SMEM 49152

__global__ __launch_bounds__(128, 4) void energy_kernel(float* __restrict__ out)
{
    extern __shared__ char smem[];
    const u32 sb = smem_u32(smem);

    const int t = threadIdx.x;
    const int wid = t >> 5, lid = t & 31;
    const int wm = wid & 1, wn = wid >> 1;

    const int js = (int)(((long long)blockIdx.x * TOTAL_JOBS) / EGRID);
    const int je = (int)(((long long)(blockIdx.x + 1) * TOTAL_JOBS) / EGRID);

    const int lc16 = t & 7;
    const int row16 = t >> 3;     // + 16*l

    const u32 lxor  = ((u32)(lid & 7)) << 4;
    const u32 abase = (u32)((wm * 32) + (lid & 7) + ((lid >> 3) & 1) * 8) * 128;
    const u32 ach   = ((u32)(lid >> 4) & 1) * 16;
    const u32 bbase4 = (u32)((wn * 32) + ((lid >> 4) & 1) * 8 + (lid & 7)) * 128;
    const u32 bk4    = ((u32)(lid >> 3) & 1) * 16;

    // prefetch K for first job
    {
        int job = js;
        int ib = job >> 6;
        size_t krow0 = (size_t)(ib >> 6) * S_DIM + (size_t)(job & 63) * 64;
        u32 kb = sb + E_K;
        #pragma unroll
        for (int l = 0; l < 4; ++l) {
            int row = row16 + 16 * l;
            u32 off = (u32)row * 128 + (u32)lc16 * 16;
            u32 swo = off ^ ((off >> 3) & 0x70);
            cp16(kb + swo, (const char*)(g_Khi + (krow0 + row) * D_DIM) + lc16 * 16);
            cp16(kb + 8192 + swo, (const char*)(g_Klo + (krow0 + row) * D_DIM) + lc16 * 16);
        }
        cp_commit();
    }

    int curIb = -1;
    u32 afH[4][2][4];   // hoisted A-hi fragments: [ks][mt][4]

    for (int job = js; job < je; ++job) {
        const int ib = job >> 6;
        const int jt = job & 63;
        const int buf = (job - js) & 1;
        const u32 kb = sb + E_K + buf * 16384;

        cp_wait0();
        __syncthreads();

        if (ib != curIb) {
            size_t qrow0 = (size_t)ib * 64;
            #pragma unroll
            for (int l = 0; l < 4; ++l) {
                int row = row16 + 16 * l;
                u32 off = (u32)row * 128 + (u32)lc16 * 16;
                u32 swo = off ^ ((off >> 3) & 0x70);
                *(uint4*)(smem + E_Q + swo) =
                    *(const uint4*)((const char*)(g_Qhi + (qrow0 + row) * D_DIM) + lc16 * 16);
                *(uint4*)(smem + E_Q + 8192 + swo) =
                    *(const uint4*)((const char*)(g_Qlo + (qrow0 + row) * D_DIM) + lc16 * 16);
            }
            curIb = ib;
            __syncthreads();
            #pragma unroll
            for (int ks = 0; ks < 4; ++ks) {
                const u32 akb = ((u32)(ks * 32) + ach) ^ lxor;
                #pragma unroll
                for (int mt = 0; mt < 2; ++mt)
                    ldsm_x4(afH[ks][mt][0], afH[ks][mt][1], afH[ks][mt][2], afH[ks][mt][3],
                            sb + E_Q + abase + mt * 2048 + akb);
            }
        }

        // prefetch next K (overlaps MMA)
        if (job + 1 < je) {
            int nj = job + 1;
            int nib = nj >> 6;
            size_t krow0 = (size_t)(nib >> 6) * S_DIM + (size_t)(nj & 63) * 64;
            u32 nkb = sb + E_K + (buf ^ 1) * 16384;
            #pragma unroll
            for (int l = 0; l < 4; ++l) {
                int row = row16 + 16 * l;
                u32 off = (u32)row * 128 + (u32)lc16 * 16;
                u32 swo = off ^ ((off >> 3) & 0x70);
                cp16(nkb + swo, (const char*)(g_Khi + (krow0 + row) * D_DIM) + lc16 * 16);
                cp16(nkb + 8192 + swo, (const char*)(g_Klo + (krow0 + row) * D_DIM) + lc16 * 16);
            }
            cp_commit();
        }

        // ---- fused 3-pass MMA: afH hoisted, B via x4, aL per job ----
        float acc[2][4][4] = {};
        #pragma unroll
        for (int ks = 0; ks < 4; ++ks) {
            const u32 akb = ((u32)(ks * 32) + ach) ^ lxor;
            const u32 bkb = ((u32)(ks * 32) + bk4) ^ lxor;
            u32 bH[8], bL[8], aL[2][4];
            ldsm_x4(bH[0], bH[1], bH[2], bH[3], kb + bbase4 + bkb);
            ldsm_x4(bH[4], bH[5], bH[6], bH[7], kb + bbase4 + 2048 + bkb);
            #pragma unroll
            for (int mt = 0; mt < 2; ++mt)
                #pragma unroll
                for (int nt = 0; nt < 4; ++nt)
                    mma16816(acc[mt][nt], afH[ks][mt], bH + nt * 2);
            ldsm_x4(bL[0], bL[1], bL[2], bL[3], kb + 8192 + bbase4 + bkb);
            ldsm_x4(bL[4], bL[5], bL[6], bL[7], kb + 8192 + bbase4 + 2048 + bkb);
            #pragma unroll
            for (int mt = 0; mt < 2; ++mt)
                #pragma unroll
                for (int nt = 0; nt < 4; ++nt)
                    mma16816(acc[mt][nt], afH[ks][mt], bL + nt * 2);
            #pragma unroll
            for (int mt = 0; mt < 2; ++mt)
                ldsm_x4(aL[mt][0], aL[mt][1], aL[mt][2], aL[mt][3],
                        sb + E_Q + 8192 + abase + mt * 2048 + akb);
            #pragma unroll
            for (int mt = 0; mt < 2; ++mt)
                #pragma unroll
                for (int nt = 0; nt < 4; ++nt)
                    mma16816(acc[mt][nt], aL[mt], bH + nt * 2);
        }

        // ---- epilogue: v * rcp(|i-j|), shuffle-packed to STG.128 ----
        const int iPos0 = (ib & 63) * 64;
        const int jj0 = jt * 64;
        const int g = lid >> 2, tg = lid & 3;
        const int colbase = ((tg & 1) << 3) + ((tg & 2) << 1);  // 0,8,4,12
        float* ob = out + ((size_t)ib * 64) * S_DIM + jj0;
        #pragma unroll
        for (int mt = 0; mt < 2; ++mt) {
            #pragma unroll
            for (int half = 0; half < 2; ++half) {
                int il = wm * 32 + mt * 16 + g + half * 8;
                int ip = iPos0 + il;
                float* orow = ob + (size_t)il * S_DIM;
                #pragma unroll
                for (int grp = 0; grp < 2; ++grp) {
                    const int nt0 = grp * 2, nt1 = grp * 2 + 1;
                    int jx = jj0 + wn * 32 + nt0 * 8 + tg * 2;
                    float Xx = acc[mt][nt0][half*2+0] * fast_rcp(fmaxf(fabsf((float)(ip - jx)), 1.f));
                    float Xy = acc[mt][nt0][half*2+1] * fast_rcp(fmaxf(fabsf((float)(ip - jx - 1)), 1.f));
                    float Yx = acc[mt][nt1][half*2+0] * fast_rcp(fmaxf(fabsf((float)(ip - jx - 8)), 1.f));
                    float Yy = acc[mt][nt1][half*2+1] * fast_rcp(fmaxf(fabsf((float)(ip - jx - 9)), 1.f));
                    float pXx = __shfl_xor_sync(0xffffffffu, Xx, 1);
                    float pXy = __shfl_xor_sync(0xffffffffu, Xy, 1);
                    float pYx = __shfl_xor_sync(0xffffffffu, Yx, 1);
                    float pYy = __shfl_xor_sync(0xffffffffu, Yy, 1);
                    float4 F = (tg & 1) ? make_float4(pYx, pYy, Yx, Yy)
                                        : make_float4(Xx, Xy, pXx, pXy);
                    int col = wn * 32 + grp * 16 + colbase;
                    *(float4*)(orow + col) = F;
                }
            }
        }
    }
}

extern "C" void kernel_launch(void* const* d_in, const int* in_sizes, int n_in,
                              void* d_out, int out_size) {
    const float* feat = (const float*)d_in[0];
    const float* Wq   = (const float*)d_in[1];
    const float* Wk   = (const float*)d_in[2];
    const float* wch  = (const float*)d_in[3];
    const float* bch  = (const float*)d_in[4];
    const float* ls   = (const float*)d_in[5];
    float* out = (float*)d_out;

    cudaFuncSetAttribute(proj_kernel, cudaFuncAttributeMaxDynamicSharedMemorySize, P_SMEM);
    cudaFuncSetAttribute(energy_kernel, cudaFuncAttributeMaxDynamicSharedMemorySize, E_SMEM);

    wsetup_kernel<<<32, 256>>>(Wq, Wk);
    proj_kernel<<<(B_DIM * S_DIM) / 64, 256, P_SMEM>>>(feat, wch, bch, ls);
    energy_kernel<<<EGRID, 128, E_SMEM>>>(out);
}

// round 12
// speedup vs baseline: 1.4684x; 1.3526x over previous
#include <cuda_runtime.h>
#include <cuda_bf16.h>
#include <cuda_fp16.h>

#define B_DIM 4
#define S_DIM 4096
#define F_DIM 512
#define D_DIM 64
#define EGRID 608
#define TOTAL_JOBS 16384   // 256 i-blocks(64) x 64 j-tiles(64)

// ---------------- scratch (no cudaMalloc allowed) ----------------
__device__ __half g_Qh[B_DIM * S_DIM * D_DIM];
__device__ __half g_Kh[B_DIM * S_DIM * D_DIM];
__device__ unsigned char g_Whs[8 * 16384];   // pre-swizzled W hi tiles (bf16)
__device__ unsigned char g_Wls[8 * 16384];   // pre-swizzled W lo tiles (bf16)

typedef unsigned long long u64;
typedef unsigned u32;

__device__ __forceinline__ float fast_rcp(float x) {
    float r; asm("rcp.approx.f32 %0, %1;" : "=f"(r) : "f"(x)); return r;
}
__device__ __forceinline__ u32 smem_u32(const void* p) {
    u32 a;
    asm("{ .reg .u64 t; cvta.to.shared.u64 t, %1; cvt.u32.u64 %0, t; }" : "=r"(a) : "l"(p));
    return a;
}
__device__ __forceinline__ void ldsm_x4(u32& r0, u32& r1, u32& r2, u32& r3, u32 addr) {
    asm volatile("ldmatrix.sync.aligned.m8n8.x4.shared.b16 {%0,%1,%2,%3}, [%4];"
                 : "=r"(r0), "=r"(r1), "=r"(r2), "=r"(r3) : "r"(addr));
}
// bf16 MMA (used by proj's high-accuracy internal GEMM)
__device__ __forceinline__ void mma16816(float* c, const u32* a, const u32* b) {
    asm volatile(
        "mma.sync.aligned.m16n8k16.row.col.f32.bf16.bf16.f32 "
        "{%0,%1,%2,%3}, {%4,%5,%6,%7}, {%8,%9}, {%0,%1,%2,%3};"
        : "+f"(c[0]), "+f"(c[1]), "+f"(c[2]), "+f"(c[3])
        : "r"(a[0]), "r"(a[1]), "r"(a[2]), "r"(a[3]), "r"(b[0]), "r"(b[1]));
}
// fp16 MMA (energy single-pass)
__device__ __forceinline__ void mma16816h(float* c, const u32* a, const u32* b) {
    asm volatile(
        "mma.sync.aligned.m16n8k16.row.col.f32.f16.f16.f32 "
        "{%0,%1,%2,%3}, {%4,%5,%6,%7}, {%8,%9}, {%0,%1,%2,%3};"
        : "+f"(c[0]), "+f"(c[1]), "+f"(c[2]), "+f"(c[3])
        : "r"(a[0]), "r"(a[1]), "r"(a[2]), "r"(a[3]), "r"(b[0]), "r"(b[1]));
}
__device__ __forceinline__ void cp16(u32 dst, const void* src) {
    asm volatile("cp.async.cg.shared.global [%0], [%1], 16;" :: "r"(dst), "l"(src));
}
__device__ __forceinline__ void cp_commit() { asm volatile("cp.async.commit_group;" ::: "memory"); }
__device__ __forceinline__ void cp_wait0()  { asm volatile("cp.async.wait_group 0;" ::: "memory"); }
__device__ __forceinline__ void cp_wait1()  { asm volatile("cp.async.wait_group 1;" ::: "memory"); }

__device__ __forceinline__ void split2(float x, float y, u32& h, u32& l) {
    __nv_bfloat162 hh = __floats2bfloat162_rn(x, y);
    float rx = x - __bfloat162float(hh.x);
    float ry = y - __bfloat162float(hh.y);
    __nv_bfloat162 ll = __floats2bfloat162_rn(rx, ry);
    h = *(u32*)&hh; l = *(u32*)&ll;
}

// =================================================================
// W setup: split Wq|Wk to bf16 hi/lo pre-swizzled tile images
// =================================================================
__global__ __launch_bounds__(256) void wsetup_kernel(
    const float* __restrict__ Wq, const float* __restrict__ Wk)
{
    int idx = blockIdx.x * 256 + threadIdx.x;   // 8192 items
    int c = idx >> 10;
    int j = (idx >> 3) & 127;
    int a = idx & 7;
    const float* wp = (j < 64) ? (Wq + j) : (Wk + (j - 64));
    int f0 = c * 64 + a * 8;
    float wv[8];
    #pragma unroll
    for (int k = 0; k < 8; ++k) wv[k] = wp[(size_t)(f0 + k) * D_DIM];
    uint4 H, L;
    split2(wv[0], wv[1], H.x, L.x);
    split2(wv[2], wv[3], H.y, L.y);
    split2(wv[4], wv[5], H.z, L.z);
    split2(wv[6], wv[7], H.w, L.w);
    u32 off = (u32)j * 128 + (u32)a * 16;
    u32 swo = off ^ ((off >> 3) & 0x70);
    *(uint4*)(g_Whs + c * 16384 + swo) = H;
    *(uint4*)(g_Wls + c * 16384 + swo) = L;
}

// =================================================================
// proj: 64-row tiles, grid 256, 2 CTAs/SM. HMMA [64] x [128 = Q|K],
// bf16 3-pass internal; emits SINGLE fp16 Q/K with scales folded in.
// =================================================================
#define P_FHI 0
#define P_FLO 8192
#define P_W   16384
#define P_WCS 81920
#define P_CHR 82432
#define P_SMEM 82944

__global__ __launch_bounds__(256, 2) void proj_kernel(
    const float* __restrict__ feat, const float* __restrict__ wch,
    const float* __restrict__ bch, const float* __restrict__ loc_p)
{
    extern __shared__ char smem[];
    const u32 sb = smem_u32(smem);
    float* wcs   = (float*)(smem + P_WCS);
    float* chRow = (float*)(smem + P_CHR);

    const int t = threadIdx.x;
    const int wid = t >> 5, lid = t & 31;
    const int wm = wid & 1, wn = wid >> 1;
    const int rowBase = blockIdx.x * 64;

    const int fr = t >> 2, ffo = (t & 3) * 16;
    const int watom = t * 16;

    if (t < 64) wcs[t] = wch[t];

    const u32 lxor  = ((u32)(lid & 7)) << 4;
    const u32 abase = (u32)((wm * 32) + (lid & 7) + ((lid >> 3) & 1) * 8) * 128;
    const u32 ach   = ((u32)(lid >> 4) & 1) * 16;
    const u32 bbase4 = (u32)((wn * 32) + ((lid >> 4) & 1) * 8 + (lid & 7)) * 128;
    const u32 bk4    = ((u32)(lid >> 3) & 1) * 16;

    float acc[2][4][4] = {};
    float csum = 0.f;

    {
        u32 wb = sb + P_W;
        #pragma unroll
        for (int a = 0; a < 4; ++a) {
            cp16(wb + watom + a * 4096, g_Whs + watom + a * 4096);
            cp16(wb + 16384 + watom + a * 4096, g_Wls + watom + a * 4096);
        }
        cp_commit();
    }

    for (int c = 0; c < 8; ++c) {
        const int f0 = c * 64;
        const u32 wb = sb + P_W + (c & 1) * 32768;
        __syncthreads();
        const float* wc_cur = wcs + (c & 1) * 64;
        {
            const float* fp = feat + (size_t)(rowBase + fr) * F_DIM + f0 + ffo;
            #pragma unroll
            for (int a = 0; a < 2; ++a) {
                float4 v0 = *(const float4*)(fp + a * 8);
                float4 v1 = *(const float4*)(fp + a * 8 + 4);
                csum += v0.x * wc_cur[ffo + a*8 + 0] + v0.y * wc_cur[ffo + a*8 + 1]
                      + v0.z * wc_cur[ffo + a*8 + 2] + v0.w * wc_cur[ffo + a*8 + 3]
                      + v1.x * wc_cur[ffo + a*8 + 4] + v1.y * wc_cur[ffo + a*8 + 5]
                      + v1.z * wc_cur[ffo + a*8 + 6] + v1.w * wc_cur[ffo + a*8 + 7];
                uint4 H, L;
                split2(v0.x, v0.y, H.x, L.x);
                split2(v0.z, v0.w, H.y, L.y);
                split2(v1.x, v1.y, H.z, L.z);
                split2(v1.z, v1.w, H.w, L.w);
                u32 off = (u32)fr * 128 + (u32)(ffo + a * 8) * 2;
                u32 swo = off ^ ((off >> 3) & 0x70);
                *(uint4*)(smem + P_FHI + swo) = H;
                *(uint4*)(smem + P_FLO + swo) = L;
            }
        }
        if (c + 1 < 8) {
            u32 nwb = sb + P_W + ((c + 1) & 1) * 32768;
            const unsigned char* gh = g_Whs + (c + 1) * 16384;
            const unsigned char* gl = g_Wls + (c + 1) * 16384;
            #pragma unroll
            for (int a = 0; a < 4; ++a) {
                cp16(nwb + watom + a * 4096, gh + watom + a * 4096);
                cp16(nwb + 16384 + watom + a * 4096, gl + watom + a * 4096);
            }
            cp_commit();
            cp_wait1();
        } else {
            cp_wait0();
        }
        if (t < 64 && c + 1 < 8) wcs[((c + 1) & 1) * 64 + t] = wch[f0 + 64 + t];
        __syncthreads();

        #pragma unroll
        for (int ks = 0; ks < 4; ++ks) {
            const u32 akb = ((u32)(ks * 32) + ach) ^ lxor;
            const u32 bkb = ((u32)(ks * 32) + bk4) ^ lxor;
            u32 afH[2][4], afL[2][4], bH[8], bL[8];
            #pragma unroll
            for (int mt = 0; mt < 2; ++mt)
                ldsm_x4(afH[mt][0], afH[mt][1], afH[mt][2], afH[mt][3],
                        sb + P_FHI + abase + mt * 2048 + akb);
            ldsm_x4(bH[0], bH[1], bH[2], bH[3], wb + bbase4 + bkb);
            ldsm_x4(bH[4], bH[5], bH[6], bH[7], wb + bbase4 + 2048 + bkb);
            #pragma unroll
            for (int mt = 0; mt < 2; ++mt)
                #pragma unroll
                for (int nt = 0; nt < 4; ++nt)
                    mma16816(acc[mt][nt], afH[mt], bH + nt * 2);
            ldsm_x4(bL[0], bL[1], bL[2], bL[3], wb + 16384 + bbase4 + bkb);
            ldsm_x4(bL[4], bL[5], bL[6], bL[7], wb + 16384 + bbase4 + 2048 + bkb);
            #pragma unroll
            for (int mt = 0; mt < 2; ++mt)
                #pragma unroll
                for (int nt = 0; nt < 4; ++nt)
                    mma16816(acc[mt][nt], afH[mt], bL + nt * 2);
            #pragma unroll
            for (int mt = 0; mt < 2; ++mt)
                ldsm_x4(afL[mt][0], afL[mt][1], afL[mt][2], afL[mt][3],
                        sb + P_FLO + abase + mt * 2048 + akb);
            #pragma unroll
            for (int mt = 0; mt < 2; ++mt)
                #pragma unroll
                for (int nt = 0; nt < 4; ++nt)
                    mma16816(acc[mt][nt], afL[mt], bH + nt * 2);
        }
    }

    csum += __shfl_xor_sync(0xffffffffu, csum, 1);
    csum += __shfl_xor_sync(0xffffffffu, csum, 2);
    if ((t & 3) == 0) chRow[fr] = 1.f / (1.f + expf(-(csum + bch[0])));
    __syncthreads();

    const float nls = -0.125f * loc_p[0];
    const int g = lid >> 2, tg = lid & 3;
    #pragma unroll
    for (int mt = 0; mt < 2; ++mt) {
        #pragma unroll
        for (int half = 0; half < 2; ++half) {
            int il = wm * 32 + mt * 16 + g + half * 8;
            size_t row = (size_t)(rowBase + il);
            float cr = chRow[il];
            #pragma unroll
            for (int nt = 0; nt < 4; ++nt) {
                int jl = wn * 32 + nt * 8 + tg * 2;
                float sc = (jl < 64) ? (nls * cr) : cr;
                float c0 = acc[mt][nt][half * 2 + 0] * sc;
                float c1 = acc[mt][nt][half * 2 + 1] * sc;
                __half2 h2 = __floats2half2_rn(c0, c1);
                if (jl < 64) {
                    *(__half2*)&g_Qh[row * D_DIM + jl] = h2;
                } else {
                    *(__half2*)&g_Kh[row * D_DIM + jl - 64] = h2;
                }
            }
        }
    }
}

// =================================================================
// energy: persistent, 4 CTAs/SM (128 threads), job tile 64(i) x 64(j)
// SINGLE-PASS fp16 MMA; all A fragments register-hoisted per i-block;
// K double-buffered cp.async; shuffle-packed STG.128 epilogue.
// smem: Q 0(8K), Kbuf0 8K, Kbuf1 16K -> 24KB
// =================================================================
#define E_Q 0
#define E_K 8192
#define E_SMEM 24576

__global__ __launch_bounds__(128, 4) void energy_kernel(float* __restrict__ out)
{
    extern __shared__ char smem[];
    const u32 sb = smem_u32(smem);

    const int t = threadIdx.x;
    const int wid = t >> 5, lid = t & 31;
    const int wm = wid & 1, wn = wid >> 1;

    const int js = (int)(((long long)blockIdx.x * TOTAL_JOBS) / EGRID);
    const int je = (int)(((long long)(blockIdx.x + 1) * TOTAL_JOBS) / EGRID);

    const int lc16 = t & 7;
    const int row16 = t >> 3;     // + 16*l

    const u32 lxor  = ((u32)(lid & 7)) << 4;
    const u32 abase = (u32)((wm * 32) + (lid & 7) + ((lid >> 3) & 1) * 8) * 128;
    const u32 ach   = ((u32)(lid >> 4) & 1) * 16;
    const u32 bbase4 = (u32)((wn * 32) + ((lid >> 4) & 1) * 8 + (lid & 7)) * 128;
    const u32 bk4    = ((u32)(lid >> 3) & 1) * 16;

    // prefetch K for first job
    {
        int job = js;
        int ib = job >> 6;
        size_t krow0 = (size_t)(ib >> 6) * S_DIM + (size_t)(job & 63) * 64;
        u32 kb = sb + E_K;
        #pragma unroll
        for (int l = 0; l < 4; ++l) {
            int row = row16 + 16 * l;
            u32 off = (u32)row * 128 + (u32)lc16 * 16;
            u32 swo = off ^ ((off >> 3) & 0x70);
            cp16(kb + swo, (const char*)(g_Kh + (krow0 + row) * D_DIM) + lc16 * 16);
        }
        cp_commit();
    }

    int curIb = -1;
    u32 afH[4][2][4];   // hoisted A fragments: [ks][mt][4]

    for (int job = js; job < je; ++job) {
        const int ib = job >> 6;
        const int jt = job & 63;
        const int buf = (job - js) & 1;
        const u32 kb = sb + E_K + buf * 8192;

        cp_wait0();
        __syncthreads();

        if (ib != curIb) {
            size_t qrow0 = (size_t)ib * 64;
            #pragma unroll
            for (int l = 0; l < 4; ++l) {
                int row = row16 + 16 * l;
                u32 off = (u32)row * 128 + (u32)lc16 * 16;
                u32 swo = off ^ ((off >> 3) & 0x70);
                *(uint4*)(smem + E_Q + swo) =
                    *(const uint4*)((const char*)(g_Qh + (qrow0 + row) * D_DIM) + lc16 * 16);
            }
            curIb = ib;
            __syncthreads();
            #pragma unroll
            for (int ks = 0; ks < 4; ++ks) {
                const u32 akb = ((u32)(ks * 32) + ach) ^ lxor;
                #pragma unroll
                for (int mt = 0; mt < 2; ++mt)
                    ldsm_x4(afH[ks][mt][0], afH[ks][mt][1], afH[ks][mt][2], afH[ks][mt][3],
                            sb + E_Q + abase + mt * 2048 + akb);
            }
        }

        // prefetch next K (overlaps MMA)
        if (job + 1 < je) {
            int nj = job + 1;
            int nib = nj >> 6;
            size_t krow0 = (size_t)(nib >> 6) * S_DIM + (size_t)(nj & 63) * 64;
            u32 nkb = sb + E_K + (buf ^ 1) * 8192;
            #pragma unroll
            for (int l = 0; l < 4; ++l) {
                int row = row16 + 16 * l;
                u32 off = (u32)row * 128 + (u32)lc16 * 16;
                u32 swo = off ^ ((off >> 3) & 0x70);
                cp16(nkb + swo, (const char*)(g_Kh + (krow0 + row) * D_DIM) + lc16 * 16);
            }
            cp_commit();
        }

        // ---- single-pass fp16 MMA, A hoisted ----
        float acc[2][4][4] = {};
        #pragma unroll
        for (int ks = 0; ks < 4; ++ks) {
            const u32 bkb = ((u32)(ks * 32) + bk4) ^ lxor;
            u32 bH[8];
            ldsm_x4(bH[0], bH[1], bH[2], bH[3], kb + bbase4 + bkb);
            ldsm_x4(bH[4], bH[5], bH[6], bH[7], kb + bbase4 + 2048 + bkb);
            #pragma unroll
            for (int mt = 0; mt < 2; ++mt)
                #pragma unroll
                for (int nt = 0; nt < 4; ++nt)
                    mma16816h(acc[mt][nt], afH[ks][mt], bH + nt * 2);
        }

        // ---- epilogue: v * rcp(|i-j|), shuffle-packed to STG.128 ----
        const int iPos0 = (ib & 63) * 64;
        const int jj0 = jt * 64;
        const int g = lid >> 2, tg = lid & 3;
        const int colbase = ((tg & 1) << 3) + ((tg & 2) << 1);  // 0,8,4,12
        float* ob = out + ((size_t)ib * 64) * S_DIM + jj0;
        #pragma unroll
        for (int mt = 0; mt < 2; ++mt) {
            #pragma unroll
            for (int half = 0; half < 2; ++half) {
                int il = wm * 32 + mt * 16 + g + half * 8;
                int ip = iPos0 + il;
                float* orow = ob + (size_t)il * S_DIM;
                #pragma unroll
                for (int grp = 0; grp < 2; ++grp) {
                    const int nt0 = grp * 2, nt1 = grp * 2 + 1;
                    int jx = jj0 + wn * 32 + nt0 * 8 + tg * 2;
                    float Xx = acc[mt][nt0][half*2+0] * fast_rcp(fmaxf(fabsf((float)(ip - jx)), 1.f));
                    float Xy = acc[mt][nt0][half*2+1] * fast_rcp(fmaxf(fabsf((float)(ip - jx - 1)), 1.f));
                    float Yx = acc[mt][nt1][half*2+0] * fast_rcp(fmaxf(fabsf((float)(ip - jx - 8)), 1.f));
                    float Yy = acc[mt][nt1][half*2+1] * fast_rcp(fmaxf(fabsf((float)(ip - jx - 9)), 1.f));
                    float pXx = __shfl_xor_sync(0xffffffffu, Xx, 1);
                    float pXy = __shfl_xor_sync(0xffffffffu, Xy, 1);
                    float pYx = __shfl_xor_sync(0xffffffffu, Yx, 1);
                    float pYy = __shfl_xor_sync(0xffffffffu, Yy, 1);
                    float4 F = (tg & 1) ? make_float4(pYx, pYy, Yx, Yy)
                                        : make_float4(Xx, Xy, pXx, pXy);
                    int col = wn * 32 + grp * 16 + colbase;
                    *(float4*)(orow + col) = F;
                }
            }
        }
    }
}

extern "C" void kernel_launch(void* const* d_in, const int* in_sizes, int n_in,
                              void* d_out, int out_size) {
    const float* feat = (const float*)d_in[0];
    const float* Wq   = (const float*)d_in[1];
    const float* Wk   = (const float*)d_in[2];
    const float* wch  = (const float*)d_in[3];
    const float* bch  = (const float*)d_in[4];
    const float* ls   = (const float*)d_in[5];
    float* out = (float*)d_out;

    cudaFuncSetAttribute(proj_kernel, cudaFuncAttributeMaxDynamicSharedMemorySize, P_SMEM);
    cudaFuncSetAttribute(energy_kernel, cudaFuncAttributeMaxDynamicSharedMemorySize, E_SMEM);

    wsetup_kernel<<<32, 256>>>(Wq, Wk);
    proj_kernel<<<(B_DIM * S_DIM) / 64, 256, P_SMEM>>>(feat, wch, bch, ls);
    energy_kernel<<<EGRID, 128, E_SMEM>>>(out);
}

// round 14
// speedup vs baseline: 1.5241x; 1.0379x over previous
#include <cuda_runtime.h>
#include <cuda_bf16.h>
#include <cuda_fp16.h>

#define B_DIM 4
#define S_DIM 4096
#define F_DIM 512
#define D_DIM 64
#define EGRID 608
#define TOTAL_JOBS 16384   // 256 i-blocks(64) x 64 j-tiles(64)

// ---------------- scratch (no cudaMalloc allowed) ----------------
__device__ __half g_Qh[B_DIM * S_DIM * D_DIM];
__device__ __half g_Kh[B_DIM * S_DIM * D_DIM];
__device__ unsigned char g_Whs[8 * 16384];   // pre-swizzled W hi tiles (fp16)
__device__ unsigned char g_Wls[8 * 16384];   // pre-swizzled W lo tiles (fp16)
__device__ float2 g_rcp[8192];               // (1/max(|k-4096|,1), 1/max(|k-4097|,1))

typedef unsigned long long u64;
typedef unsigned u32;

__device__ __forceinline__ float fast_rcp(float x) {
    float r; asm("rcp.approx.f32 %0, %1;" : "=f"(r) : "f"(x)); return r;
}
__device__ __forceinline__ u32 smem_u32(const void* p) {
    u32 a;
    asm("{ .reg .u64 t; cvta.to.shared.u64 t, %1; cvt.u32.u64 %0, t; }" : "=r"(a) : "l"(p));
    return a;
}
__device__ __forceinline__ void ldsm_x4(u32& r0, u32& r1, u32& r2, u32& r3, u32 addr) {
    asm volatile("ldmatrix.sync.aligned.m8n8.x4.shared.b16 {%0,%1,%2,%3}, [%4];"
                 : "=r"(r0), "=r"(r1), "=r"(r2), "=r"(r3) : "r"(addr));
}
// fp16 MMA, fp32 accumulate
__device__ __forceinline__ void mma16816h(float* c, const u32* a, const u32* b) {
    asm volatile(
        "mma.sync.aligned.m16n8k16.row.col.f32.f16.f16.f32 "
        "{%0,%1,%2,%3}, {%4,%5,%6,%7}, {%8,%9}, {%0,%1,%2,%3};"
        : "+f"(c[0]), "+f"(c[1]), "+f"(c[2]), "+f"(c[3])
        : "r"(a[0]), "r"(a[1]), "r"(a[2]), "r"(a[3]), "r"(b[0]), "r"(b[1]));
}
__device__ __forceinline__ void cp16(u32 dst, const void* src) {
    asm volatile("cp.async.cg.shared.global [%0], [%1], 16;" :: "r"(dst), "l"(src));
}
__device__ __forceinline__ void cp_commit() { asm volatile("cp.async.commit_group;" ::: "memory"); }
__device__ __forceinline__ void cp_wait0()  { asm volatile("cp.async.wait_group 0;" ::: "memory"); }
__device__ __forceinline__ void cp_wait1()  { asm volatile("cp.async.wait_group 1;" ::: "memory"); }

// split fp32 pair -> packed fp16 hi + residual lo
__device__ __forceinline__ void split2h(float x, float y, u32& h, u32& l) {
    __half2 hh = __floats2half2_rn(x, y);
    float rx = x - __half2float(__low2half(hh));
    float ry = y - __half2float(__high2half(hh));
    __half2 ll = __floats2half2_rn(rx, ry);
    h = *(u32*)&hh; l = *(u32*)&ll;
}

// =================================================================
// W setup: split Wq|Wk to fp16 hi/lo pre-swizzled tile images
// + reciprocal-distance table
// =================================================================
__global__ __launch_bounds__(256) void wsetup_kernel(
    const float* __restrict__ Wq, const float* __restrict__ Wk)
{
    int idx = blockIdx.x * 256 + threadIdx.x;   // 8192 items
    {
        float d0 = fmaxf(fabsf((float)(idx - 4096)), 1.f);
        float d1 = fmaxf(fabsf((float)(idx - 4097)), 1.f);
        float2 r;
        r.x = fast_rcp(d0);
        r.y = fast_rcp(d1);
        g_rcp[idx] = r;
    }
    int c = idx >> 10;
    int j = (idx >> 3) & 127;
    int a = idx & 7;
    const float* wp = (j < 64) ? (Wq + j) : (Wk + (j - 64));
    int f0 = c * 64 + a * 8;
    float wv[8];
    #pragma unroll
    for (int k = 0; k < 8; ++k) wv[k] = wp[(size_t)(f0 + k) * D_DIM];
    uint4 H, L;
    split2h(wv[0], wv[1], H.x, L.x);
    split2h(wv[2], wv[3], H.y, L.y);
    split2h(wv[4], wv[5], H.z, L.z);
    split2h(wv[6], wv[7], H.w, L.w);
    u32 off = (u32)j * 128 + (u32)a * 16;
    u32 swo = off ^ ((off >> 3) & 0x70);
    *(uint4*)(g_Whs + c * 16384 + swo) = H;
    *(uint4*)(g_Wls + c * 16384 + swo) = L;
}

// =================================================================
// proj: 64-row tiles, grid 256, 2 CTAs/SM. fp16 2-pass HMMA
// [64] x [128 = Q|K]: F·Whi + F·Wlo (W exact, feat single-fp16).
// smem: F 0(8K), Wbuf 8K(2 x {hi16K, lo16K}), wcs 72K, chRow +512
// =================================================================
#define P_F   0
#define P_W   8192
#define P_WCS 73728
#define P_CHR 74240
#define P_SMEM 74752

__global__ __launch_bounds__(256, 2) void proj_kernel(
    const float* __restrict__ feat, const float* __restrict__ wch,
    const float* __restrict__ bch, const float* __restrict__ loc_p)
{
    extern __shared__ char smem[];
    const u32 sb = smem_u32(smem);
    float* wcs   = (float*)(smem + P_WCS);
    float* chRow = (float*)(smem + P_CHR);

    const int t = threadIdx.x;
    const int wid = t >> 5, lid = t & 31;
    const int wm = wid & 1, wn = wid >> 1;
    const int rowBase = blockIdx.x * 64;

    const int fr = t >> 2, ffo = (t & 3) * 16;
    const int watom = t * 16;

    if (t < 64) wcs[t] = wch[t];

    const u32 lxor  = ((u32)(lid & 7)) << 4;
    const u32 abase = (u32)((wm * 32) + (lid & 7) + ((lid >> 3) & 1) * 8) * 128;
    const u32 ach   = ((u32)(lid >> 4) & 1) * 16;
    const u32 bbase4 = (u32)((wn * 32) + ((lid >> 4) & 1) * 8 + (lid & 7)) * 128;
    const u32 bk4    = ((u32)(lid >> 3) & 1) * 16;

    float acc[2][4][4] = {};
    float csum = 0.f;

    // prefetch W chunk 0 into buf 0
    {
        u32 wb = sb + P_W;
        #pragma unroll
        for (int a = 0; a < 4; ++a) {
            cp16(wb + watom + a * 4096, g_Whs + watom + a * 4096);
            cp16(wb + 16384 + watom + a * 4096, g_Wls + watom + a * 4096);
        }
        cp_commit();
    }

    for (int c = 0; c < 8; ++c) {
        const int f0 = c * 64;
        const u32 wb = sb + P_W + (c & 1) * 32768;
        __syncthreads();
        const float* wc_cur = wcs + (c & 1) * 64;
        // ---- feat tile: 64 rows x 64 f, fp32 -> single fp16 + charge ----
        {
            const float* fp = feat + (size_t)(rowBase + fr) * F_DIM + f0 + ffo;
            float4 v0 = *(const float4*)(fp + 0);
            float4 v1 = *(const float4*)(fp + 4);
            float4 v2 = *(const float4*)(fp + 8);
            float4 v3 = *(const float4*)(fp + 12);
            csum += v0.x * wc_cur[ffo + 0]  + v0.y * wc_cur[ffo + 1]
                  + v0.z * wc_cur[ffo + 2]  + v0.w * wc_cur[ffo + 3]
                  + v1.x * wc_cur[ffo + 4]  + v1.y * wc_cur[ffo + 5]
                  + v1.z * wc_cur[ffo + 6]  + v1.w * wc_cur[ffo + 7]
                  + v2.x * wc_cur[ffo + 8]  + v2.y * wc_cur[ffo + 9]
                  + v2.z * wc_cur[ffo + 10] + v2.w * wc_cur[ffo + 11]
                  + v3.x * wc_cur[ffo + 12] + v3.y * wc_cur[ffo + 13]
                  + v3.z * wc_cur[ffo + 14] + v3.w * wc_cur[ffo + 15];
            uint4 H0, H1;
            __half2 h;
            h = __floats2half2_rn(v0.x, v0.y); H0.x = *(u32*)&h;
            h = __floats2half2_rn(v0.z, v0.w); H0.y = *(u32*)&h;
            h = __floats2half2_rn(v1.x, v1.y); H0.z = *(u32*)&h;
            h = __floats2half2_rn(v1.z, v1.w); H0.w = *(u32*)&h;
            h = __floats2half2_rn(v2.x, v2.y); H1.x = *(u32*)&h;
            h = __floats2half2_rn(v2.z, v2.w); H1.y = *(u32*)&h;
            h = __floats2half2_rn(v3.x, v3.y); H1.z = *(u32*)&h;
            h = __floats2half2_rn(v3.z, v3.w); H1.w = *(u32*)&h;
            u32 off0 = (u32)fr * 128 + (u32)ffo * 2;
            u32 off1 = off0 + 16;
            *(uint4*)(smem + P_F + (off0 ^ ((off0 >> 3) & 0x70))) = H0;
            *(uint4*)(smem + P_F + (off1 ^ ((off1 >> 3) & 0x70))) = H1;
        }
        // prefetch next W chunk
        if (c + 1 < 8) {
            u32 nwb = sb + P_W + ((c + 1) & 1) * 32768;
            const unsigned char* gh = g_Whs + (c + 1) * 16384;
            const unsigned char* gl = g_Wls + (c + 1) * 16384;
            #pragma unroll
            for (int a = 0; a < 4; ++a) {
                cp16(nwb + watom + a * 4096, gh + watom + a * 4096);
                cp16(nwb + 16384 + watom + a * 4096, gl + watom + a * 4096);
            }
            cp_commit();
            cp_wait1();
        } else {
            cp_wait0();
        }
        if (t < 64 && c + 1 < 8) wcs[((c + 1) & 1) * 64 + t] = wch[f0 + 64 + t];
        __syncthreads();

        // ---- 2-pass fp16 MMA: F·Whi + F·Wlo ----
        #pragma unroll
        for (int ks = 0; ks < 4; ++ks) {
            const u32 akb = ((u32)(ks * 32) + ach) ^ lxor;
            const u32 bkb = ((u32)(ks * 32) + bk4) ^ lxor;
            u32 aF[2][4], bH[8], bL[8];
            #pragma unroll
            for (int mt = 0; mt < 2; ++mt)
                ldsm_x4(aF[mt][0], aF[mt][1], aF[mt][2], aF[mt][3],
                        sb + P_F + abase + mt * 2048 + akb);
            ldsm_x4(bH[0], bH[1], bH[2], bH[3], wb + bbase4 + bkb);
            ldsm_x4(bH[4], bH[5], bH[6], bH[7], wb + bbase4 + 2048 + bkb);
            #pragma unroll
            for (int mt = 0; mt < 2; ++mt)
                #pragma unroll
                for (int nt = 0; nt < 4; ++nt)
                    mma16816h(acc[mt][nt], aF[mt], bH + nt * 2);
            ldsm_x4(bL[0], bL[1], bL[2], bL[3], wb + 16384 + bbase4 + bkb);
            ldsm_x4(bL[4], bL[5], bL[6], bL[7], wb + 16384 + bbase4 + 2048 + bkb);
            #pragma unroll
            for (int mt = 0; mt < 2; ++mt)
                #pragma unroll
                for (int nt = 0; nt < 4; ++nt)
                    mma16816h(acc[mt][nt], aF[mt], bL + nt * 2);
        }
    }

    csum += __shfl_xor_sync(0xffffffffu, csum, 1);
    csum += __shfl_xor_sync(0xffffffffu, csum, 2);
    if ((t & 3) == 0) chRow[fr] = 1.f / (1.f + expf(-(csum + bch[0])));
    __syncthreads();

    const float nls = -0.125f * loc_p[0];
    const int g = lid >> 2, tg = lid & 3;
    #pragma unroll
    for (int mt = 0; mt < 2; ++mt) {
        #pragma unroll
        for (int half = 0; half < 2; ++half) {
            int il = wm * 32 + mt * 16 + g + half * 8;
            size_t row = (size_t)(rowBase + il);
            float cr = chRow[il];
            #pragma unroll
            for (int nt = 0; nt < 4; ++nt) {
                int jl = wn * 32 + nt * 8 + tg * 2;
                float sc = (jl < 64) ? (nls * cr) : cr;
                float c0 = acc[mt][nt][half * 2 + 0] * sc;
                float c1 = acc[mt][nt][half * 2 + 1] * sc;
                __half2 h2 = __floats2half2_rn(c0, c1);
                if (jl < 64) {
                    *(__half2*)&g_Qh[row * D_DIM + jl] = h2;
                } else {
                    *(__half2*)&g_Kh[row * D_DIM + jl - 64] = h2;
                }
            }
        }
    }
}

// =================================================================
// energy: persistent, 4 CTAs/SM (128 threads), job tile 64(i) x 64(j)
// single-pass fp16 MMA; A hoisted; K double-buffered cp.async;
// epilogue: rcp TABLE (no MUFU/I2F) + shuffle-packed STG.128.
// smem: Q 0(8K), Kbuf0 8K, Kbuf1 16K -> 24KB
// =================================================================
#define E_Q 0
#define E_K 8192
#define E_SMEM 24576

__global__ __launch_bounds__(128, 4) void energy_kernel(float* __restrict__ out)
{
    extern __shared__ char smem[];
    const u32 sb = smem_u32(smem);

    const int t = threadIdx.x;
    const int wid = t >> 5, lid = t & 31;
    const int wm = wid & 1, wn = wid >> 1;

    const int js = (int)(((long long)blockIdx.x * TOTAL_JOBS) / EGRID);
    const int je = (int)(((long long)(blockIdx.x + 1) * TOTAL_JOBS) / EGRID);

    const int lc16 = t & 7;
    const int row16 = t >> 3;     // + 16*l

    const u32 lxor  = ((u32)(lid & 7)) << 4;
    const u32 abase = (u32)((wm * 32) + (lid & 7) + ((lid >> 3) & 1) * 8) * 128;
    const u32 ach   = ((u32)(lid >> 4) & 1) * 16;
    const u32 bbase4 = (u32)((wn * 32) + ((lid >> 4) & 1) * 8 + (lid & 7)) * 128;
    const u32 bk4    = ((u32)(lid >> 3) & 1) * 16;

    // prefetch K for first job
    {
        int job = js;
        int ib = job >> 6;
        size_t krow0 = (size_t)(ib >> 6) * S_DIM + (size_t)(job & 63) * 64;
        u32 kb = sb + E_K;
        #pragma unroll
        for (int l = 0; l < 4; ++l) {
            int row = row16 + 16 * l;
            u32 off = (u32)row * 128 + (u32)lc16 * 16;
            u32 swo = off ^ ((off >> 3) & 0x70);
            cp16(kb + swo, (const char*)(g_Kh + (krow0 + row) * D_DIM) + lc16 * 16);
        }
        cp_commit();
    }

    int curIb = -1;
    u32 afH[4][2][4];   // hoisted A fragments: [ks][mt][4]

    for (int job = js; job < je; ++job) {
        const int ib = job >> 6;
        const int jt = job & 63;
        const int buf = (job - js) & 1;
        const u32 kb = sb + E_K + buf * 8192;

        cp_wait0();
        __syncthreads();

        if (ib != curIb) {
            size_t qrow0 = (size_t)ib * 64;
            #pragma unroll
            for (int l = 0; l < 4; ++l) {
                int row = row16 + 16 * l;
                u32 off = (u32)row * 128 + (u32)lc16 * 16;
                u32 swo = off ^ ((off >> 3) & 0x70);
                *(uint4*)(smem + E_Q + swo) =
                    *(const uint4*)((const char*)(g_Qh + (qrow0 + row) * D_DIM) + lc16 * 16);
            }
            curIb = ib;
            __syncthreads();
            #pragma unroll
            for (int ks = 0; ks < 4; ++ks) {
                const u32 akb = ((u32)(ks * 32) + ach) ^ lxor;
                #pragma unroll
                for (int mt = 0; mt < 2; ++mt)
                    ldsm_x4(afH[ks][mt][0], afH[ks][mt][1], afH[ks][mt][2], afH[ks][mt][3],
                            sb + E_Q + abase + mt * 2048 + akb);
            }
        }

        // prefetch next K (overlaps MMA)
        if (job + 1 < je) {
            int nj = job + 1;
            int nib = nj >> 6;
            size_t krow0 = (size_t)(nib >> 6) * S_DIM + (size_t)(nj & 63) * 64;
            u32 nkb = sb + E_K + (buf ^ 1) * 8192;
            #pragma unroll
            for (int l = 0; l < 4; ++l) {
                int row = row16 + 16 * l;
                u32 off = (u32)row * 128 + (u32)lc16 * 16;
                u32 swo = off ^ ((off >> 3) & 0x70);
                cp16(nkb + swo, (const char*)(g_Kh + (krow0 + row) * D_DIM) + lc16 * 16);
            }
            cp_commit();
        }

        // ---- single-pass fp16 MMA, A hoisted ----
        float acc[2][4][4] = {};
        #pragma unroll
        for (int ks = 0; ks < 4; ++ks) {
            const u32 bkb = ((u32)(ks * 32) + bk4) ^ lxor;
            u32 bH[8];
            ldsm_x4(bH[0], bH[1], bH[2], bH[3], kb + bbase4 + bkb);
            ldsm_x4(bH[4], bH[5], bH[6], bH[7], kb + bbase4 + 2048 + bkb);
            #pragma unroll
            for (int mt = 0; mt < 2; ++mt)
                #pragma unroll
                for (int nt = 0; nt < 4; ++nt)
                    mma16816h(acc[mt][nt], afH[ks][mt], bH + nt * 2);
        }

        // ---- epilogue: v * table-rcp(|i-j|), shuffle-packed STG.128 ----
        const int iPos0 = (ib & 63) * 64;
        const int jj0 = jt * 64;
        const int g = lid >> 2, tg = lid & 3;
        const int colbase = ((tg & 1) << 3) + ((tg & 2) << 1);  // 0,8,4,12
        float* ob = out + ((size_t)ib * 64) * S_DIM + jj0;
        #pragma unroll
        for (int mt = 0; mt < 2; ++mt) {
            #pragma unroll
            for (int half = 0; half < 2; ++half) {
                int il = wm * 32 + mt * 16 + g + half * 8;
                int ip = iPos0 + il;
                // table index: 4096 + (i - j) = 4096 + ip - (jj0 + jl)
                int kbase = 4096 + ip - jj0;
                float* orow = ob + (size_t)il * S_DIM;
                #pragma unroll
                for (int grp = 0; grp < 2; ++grp) {
                    int jl0 = wn * 32 + grp * 16 + tg * 2;   // X pair local col
                    float2 rX = g_rcp[kbase - jl0];
                    float2 rY = g_rcp[kbase - jl0 - 8];
                    const int nt0 = grp * 2, nt1 = grp * 2 + 1;
                    float Xx = acc[mt][nt0][half*2+0] * rX.x;
                    float Xy = acc[mt][nt0][half*2+1] * rX.y;
                    float Yx = acc[mt][nt1][half*2+0] * rY.x;
                    float Yy = acc[mt][nt1][half*2+1] * rY.y;
                    float pXx = __shfl_xor_sync(0xffffffffu, Xx, 1);
                    float pXy = __shfl_xor_sync(0xffffffffu, Xy, 1);
                    float pYx = __shfl_xor_sync(0xffffffffu, Yx, 1);
                    float pYy = __shfl_xor_sync(0xffffffffu, Yy, 1);
                    float4 F = (tg & 1) ? make_float4(pYx, pYy, Yx, Yy)
                                        : make_float4(Xx, Xy, pXx, pXy);
                    int col = wn * 32 + grp * 16 + colbase;
                    *(float4*)(orow + col) = F;
                }
            }
        }
    }
}

extern "C" void kernel_launch(void* const* d_in, const int* in_sizes, int n_in,
                              void* d_out, int out_size) {
    const float* feat = (const float*)d_in[0];
    const float* Wq   = (const float*)d_in[1];
    const float* Wk   = (const float*)d_in[2];
    const float* wch  = (const float*)d_in[3];
    const float* bch  = (const float*)d_in[4];
    const float* ls   = (const float*)d_in[5];
    float* out = (float*)d_out;

    cudaFuncSetAttribute(proj_kernel, cudaFuncAttributeMaxDynamicSharedMemorySize, P_SMEM);
    cudaFuncSetAttribute(energy_kernel, cudaFuncAttributeMaxDynamicSharedMemorySize, E_SMEM);

    wsetup_kernel<<<32, 256>>>(Wq, Wk);
    proj_kernel<<<(B_DIM * S_DIM) / 64, 256, P_SMEM>>>(feat, wch, bch, ls);
    energy_kernel<<<EGRID, 128, E_SMEM>>>(out);
}

// round 15
// speedup vs baseline: 1.6722x; 1.0971x over previous
#include <cuda_runtime.h>
#include <cuda_bf16.h>
#include <cuda_fp16.h>

#define B_DIM 4
#define S_DIM 4096
#define F_DIM 512
#define D_DIM 64
#define EGRID 608
#define TOTAL_JOBS 16384   // 256 i-blocks(64) x 64 j-tiles(64)

// ---------------- scratch (no cudaMalloc allowed) ----------------
__device__ __half g_Qh[B_DIM * S_DIM * D_DIM];
__device__ __half g_Kh[B_DIM * S_DIM * D_DIM];
__device__ unsigned char g_Whs[8 * 16384];   // pre-swizzled W fp16 tiles
__device__ float2 g_rcp[8192];               // (1/max(|k-4096|,1), 1/max(|k-4097|,1))

typedef unsigned long long u64;
typedef unsigned u32;

__device__ __forceinline__ float fast_rcp(float x) {
    float r; asm("rcp.approx.f32 %0, %1;" : "=f"(r) : "f"(x)); return r;
}
__device__ __forceinline__ u32 smem_u32(const void* p) {
    u32 a;
    asm("{ .reg .u64 t; cvta.to.shared.u64 t, %1; cvt.u32.u64 %0, t; }" : "=r"(a) : "l"(p));
    return a;
}
__device__ __forceinline__ void ldsm_x4(u32& r0, u32& r1, u32& r2, u32& r3, u32 addr) {
    asm volatile("ldmatrix.sync.aligned.m8n8.x4.shared.b16 {%0,%1,%2,%3}, [%4];"
                 : "=r"(r0), "=r"(r1), "=r"(r2), "=r"(r3) : "r"(addr));
}
// fp16 MMA, fp32 accumulate
__device__ __forceinline__ void mma16816h(float* c, const u32* a, const u32* b) {
    asm volatile(
        "mma.sync.aligned.m16n8k16.row.col.f32.f16.f16.f32 "
        "{%0,%1,%2,%3}, {%4,%5,%6,%7}, {%8,%9}, {%0,%1,%2,%3};"
        : "+f"(c[0]), "+f"(c[1]), "+f"(c[2]), "+f"(c[3])
        : "r"(a[0]), "r"(a[1]), "r"(a[2]), "r"(a[3]), "r"(b[0]), "r"(b[1]));
}
__device__ __forceinline__ void cp16(u32 dst, const void* src) {
    asm volatile("cp.async.cg.shared.global [%0], [%1], 16;" :: "r"(dst), "l"(src));
}
__device__ __forceinline__ void cp_commit() { asm volatile("cp.async.commit_group;" ::: "memory"); }
__device__ __forceinline__ void cp_wait0()  { asm volatile("cp.async.wait_group 0;" ::: "memory"); }
__device__ __forceinline__ void cp_wait1()  { asm volatile("cp.async.wait_group 1;" ::: "memory"); }

// =================================================================
// W setup: Wq|Wk -> single fp16 pre-swizzled tile images + rcp table
// =================================================================
__global__ __launch_bounds__(256) void wsetup_kernel(
    const float* __restrict__ Wq, const float* __restrict__ Wk)
{
    int idx = blockIdx.x * 256 + threadIdx.x;   // 8192 items
    {
        float d0 = fmaxf(fabsf((float)(idx - 4096)), 1.f);
        float d1 = fmaxf(fabsf((float)(idx - 4097)), 1.f);
        float2 r;
        r.x = fast_rcp(d0);
        r.y = fast_rcp(d1);
        g_rcp[idx] = r;
    }
    int c = idx >> 10;
    int j = (idx >> 3) & 127;
    int a = idx & 7;
    const float* wp = (j < 64) ? (Wq + j) : (Wk + (j - 64));
    int f0 = c * 64 + a * 8;
    float wv[8];
    #pragma unroll
    for (int k = 0; k < 8; ++k) wv[k] = wp[(size_t)(f0 + k) * D_DIM];
    uint4 H;
    __half2 h;
    h = __floats2half2_rn(wv[0], wv[1]); H.x = *(u32*)&h;
    h = __floats2half2_rn(wv[2], wv[3]); H.y = *(u32*)&h;
    h = __floats2half2_rn(wv[4], wv[5]); H.z = *(u32*)&h;
    h = __floats2half2_rn(wv[6], wv[7]); H.w = *(u32*)&h;
    u32 off = (u32)j * 128 + (u32)a * 16;
    u32 swo = off ^ ((off >> 3) & 0x70);
    *(uint4*)(g_Whs + c * 16384 + swo) = H;
}

// =================================================================
// proj: 64-row tiles, grid 256, 2 CTAs/SM. fp16 single-pass HMMA
// [64] x [128 = Q|K]; feat LDGs software-pipelined over MMA.
// smem: F 0(8K), Wbuf 8K(2x16K), wcs 40960, chRow 41472
// =================================================================
#define P_F   0
#define P_W   8192
#define P_WCS 40960
#define P_CHR 41472
#define P_SMEM 41984

__global__ __launch_bounds__(256, 2) void proj_kernel(
    const float* __restrict__ feat, const float* __restrict__ wch,
    const float* __restrict__ bch, const float* __restrict__ loc_p)
{
    extern __shared__ char smem[];
    const u32 sb = smem_u32(smem);
    float* wcs   = (float*)(smem + P_WCS);
    float* chRow = (float*)(smem + P_CHR);

    const int t = threadIdx.x;
    const int wid = t >> 5, lid = t & 31;
    const int wm = wid & 1, wn = wid >> 1;
    const int rowBase = blockIdx.x * 64;

    const int fr = t >> 2, ffo = (t & 3) * 16;
    const int watom = t * 16;

    if (t < 64) wcs[t] = wch[t];

    const u32 lxor  = ((u32)(lid & 7)) << 4;
    const u32 abase = (u32)((wm * 32) + (lid & 7) + ((lid >> 3) & 1) * 8) * 128;
    const u32 ach   = ((u32)(lid >> 4) & 1) * 16;
    const u32 bbase4 = (u32)((wn * 32) + ((lid >> 4) & 1) * 8 + (lid & 7)) * 128;
    const u32 bk4    = ((u32)(lid >> 3) & 1) * 16;

    float acc[2][4][4] = {};
    float csum = 0.f;

    // prefetch W chunk 0 into buf 0
    {
        u32 wb = sb + P_W;
        #pragma unroll
        for (int a = 0; a < 4; ++a)
            cp16(wb + watom + a * 4096, g_Whs + watom + a * 4096);
        cp_commit();
    }

    // preload feat chunk 0 into registers
    const float* fbase = feat + (size_t)(rowBase + fr) * F_DIM + ffo;
    float4 v0 = *(const float4*)(fbase + 0);
    float4 v1 = *(const float4*)(fbase + 4);
    float4 v2 = *(const float4*)(fbase + 8);
    float4 v3 = *(const float4*)(fbase + 12);

    for (int c = 0; c < 8; ++c) {
        const u32 wb = sb + P_W + (c & 1) * 16384;
        __syncthreads();
        const float* wc_cur = wcs + (c & 1) * 64;
        // ---- convert current chunk regs -> F smem + charge partial ----
        {
            csum += v0.x * wc_cur[ffo + 0]  + v0.y * wc_cur[ffo + 1]
                  + v0.z * wc_cur[ffo + 2]  + v0.w * wc_cur[ffo + 3]
                  + v1.x * wc_cur[ffo + 4]  + v1.y * wc_cur[ffo + 5]
                  + v1.z * wc_cur[ffo + 6]  + v1.w * wc_cur[ffo + 7]
                  + v2.x * wc_cur[ffo + 8]  + v2.y * wc_cur[ffo + 9]
                  + v2.z * wc_cur[ffo + 10] + v2.w * wc_cur[ffo + 11]
                  + v3.x * wc_cur[ffo + 12] + v3.y * wc_cur[ffo + 13]
                  + v3.z * wc_cur[ffo + 14] + v3.w * wc_cur[ffo + 15];
            uint4 H0, H1;
            __half2 h;
            h = __floats2half2_rn(v0.x, v0.y); H0.x = *(u32*)&h;
            h = __floats2half2_rn(v0.z, v0.w); H0.y = *(u32*)&h;
            h = __floats2half2_rn(v1.x, v1.y); H0.z = *(u32*)&h;
            h = __floats2half2_rn(v1.z, v1.w); H0.w = *(u32*)&h;
            h = __floats2half2_rn(v2.x, v2.y); H1.x = *(u32*)&h;
            h = __floats2half2_rn(v2.z, v2.w); H1.y = *(u32*)&h;
            h = __floats2half2_rn(v3.x, v3.y); H1.z = *(u32*)&h;
            h = __floats2half2_rn(v3.z, v3.w); H1.w = *(u32*)&h;
            u32 off0 = (u32)fr * 128 + (u32)ffo * 2;
            u32 off1 = off0 + 16;
            *(uint4*)(smem + P_F + (off0 ^ ((off0 >> 3) & 0x70))) = H0;
            *(uint4*)(smem + P_F + (off1 ^ ((off1 >> 3) & 0x70))) = H1;
        }
        // prefetch next W chunk
        if (c + 1 < 8) {
            u32 nwb = sb + P_W + ((c + 1) & 1) * 16384;
            const unsigned char* gh = g_Whs + (c + 1) * 16384;
            #pragma unroll
            for (int a = 0; a < 4; ++a)
                cp16(nwb + watom + a * 4096, gh + watom + a * 4096);
            cp_commit();
            cp_wait1();
        } else {
            cp_wait0();
        }
        if (t < 64 && c + 1 < 8) wcs[((c + 1) & 1) * 64 + t] = wch[(c + 1) * 64 + t];
        __syncthreads();

        // ---- issue feat LDGs for next chunk (hidden under MMA) ----
        if (c + 1 < 8) {
            const float* fp = fbase + (c + 1) * 64;
            v0 = *(const float4*)(fp + 0);
            v1 = *(const float4*)(fp + 4);
            v2 = *(const float4*)(fp + 8);
            v3 = *(const float4*)(fp + 12);
        }

        // ---- single-pass fp16 MMA: F·W ----
        #pragma unroll
        for (int ks = 0; ks < 4; ++ks) {
            const u32 akb = ((u32)(ks * 32) + ach) ^ lxor;
            const u32 bkb = ((u32)(ks * 32) + bk4) ^ lxor;
            u32 aF[2][4], bH[8];
            #pragma unroll
            for (int mt = 0; mt < 2; ++mt)
                ldsm_x4(aF[mt][0], aF[mt][1], aF[mt][2], aF[mt][3],
                        sb + P_F + abase + mt * 2048 + akb);
            ldsm_x4(bH[0], bH[1], bH[2], bH[3], wb + bbase4 + bkb);
            ldsm_x4(bH[4], bH[5], bH[6], bH[7], wb + bbase4 + 2048 + bkb);
            #pragma unroll
            for (int mt = 0; mt < 2; ++mt)
                #pragma unroll
                for (int nt = 0; nt < 4; ++nt)
                    mma16816h(acc[mt][nt], aF[mt], bH + nt * 2);
        }
    }

    csum += __shfl_xor_sync(0xffffffffu, csum, 1);
    csum += __shfl_xor_sync(0xffffffffu, csum, 2);
    if ((t & 3) == 0) chRow[fr] = 1.f / (1.f + expf(-(csum + bch[0])));
    __syncthreads();

    const float nls = -0.125f * loc_p[0];
    const int g = lid >> 2, tg = lid & 3;
    #pragma unroll
    for (int mt = 0; mt < 2; ++mt) {
        #pragma unroll
        for (int half = 0; half < 2; ++half) {
            int il = wm * 32 + mt * 16 + g + half * 8;
            size_t row = (size_t)(rowBase + il);
            float cr = chRow[il];
            #pragma unroll
            for (int nt = 0; nt < 4; ++nt) {
                int jl = wn * 32 + nt * 8 + tg * 2;
                float sc = (jl < 64) ? (nls * cr) : cr;
                float c0 = acc[mt][nt][half * 2 + 0] * sc;
                float c1 = acc[mt][nt][half * 2 + 1] * sc;
                __half2 h2 = __floats2half2_rn(c0, c1);
                if (jl < 64) {
                    *(__half2*)&g_Qh[row * D_DIM + jl] = h2;
                } else {
                    *(__half2*)&g_Kh[row * D_DIM + jl - 64] = h2;
                }
            }
        }
    }
}

// =================================================================
// energy: persistent, 4 CTAs/SM (128 threads), job tile 64(i) x 64(j)
// single-pass fp16 MMA; A hoisted; K double-buffered cp.async;
// epilogue: rcp TABLE + shuffle-packed STG.128. (unchanged from R14)
// smem: Q 0(8K), Kbuf0 8K, Kbuf1 16K -> 24KB
// =================================================================
#define E_Q 0
#define E_K 8192
#define E_SMEM 24576

__global__ __launch_bounds__(128, 4) void energy_kernel(float* __restrict__ out)
{
    extern __shared__ char smem[];
    const u32 sb = smem_u32(smem);

    const int t = threadIdx.x;
    const int wid = t >> 5, lid = t & 31;
    const int wm = wid & 1, wn = wid >> 1;

    const int js = (int)(((long long)blockIdx.x * TOTAL_JOBS) / EGRID);
    const int je = (int)(((long long)(blockIdx.x + 1) * TOTAL_JOBS) / EGRID);

    const int lc16 = t & 7;
    const int row16 = t >> 3;     // + 16*l

    const u32 lxor  = ((u32)(lid & 7)) << 4;
    const u32 abase = (u32)((wm * 32) + (lid & 7) + ((lid >> 3) & 1) * 8) * 128;
    const u32 ach   = ((u32)(lid >> 4) & 1) * 16;
    const u32 bbase4 = (u32)((wn * 32) + ((lid >> 4) & 1) * 8 + (lid & 7)) * 128;
    const u32 bk4    = ((u32)(lid >> 3) & 1) * 16;

    // prefetch K for first job
    {
        int job = js;
        int ib = job >> 6;
        size_t krow0 = (size_t)(ib >> 6) * S_DIM + (size_t)(job & 63) * 64;
        u32 kb = sb + E_K;
        #pragma unroll
        for (int l = 0; l < 4; ++l) {
            int row = row16 + 16 * l;
            u32 off = (u32)row * 128 + (u32)lc16 * 16;
            u32 swo = off ^ ((off >> 3) & 0x70);
            cp16(kb + swo, (const char*)(g_Kh + (krow0 + row) * D_DIM) + lc16 * 16);
        }
        cp_commit();
    }

    int curIb = -1;
    u32 afH[4][2][4];   // hoisted A fragments: [ks][mt][4]

    for (int job = js; job < je; ++job) {
        const int ib = job >> 6;
        const int jt = job & 63;
        const int buf = (job - js) & 1;
        const u32 kb = sb + E_K + buf * 8192;

        cp_wait0();
        __syncthreads();

        if (ib != curIb) {
            size_t qrow0 = (size_t)ib * 64;
            #pragma unroll
            for (int l = 0; l < 4; ++l) {
                int row = row16 + 16 * l;
                u32 off = (u32)row * 128 + (u32)lc16 * 16;
                u32 swo = off ^ ((off >> 3) & 0x70);
                *(uint4*)(smem + E_Q + swo) =
                    *(const uint4*)((const char*)(g_Qh + (qrow0 + row) * D_DIM) + lc16 * 16);
            }
            curIb = ib;
            __syncthreads();
            #pragma unroll
            for (int ks = 0; ks < 4; ++ks) {
                const u32 akb = ((u32)(ks * 32) + ach) ^ lxor;
                #pragma unroll
                for (int mt = 0; mt < 2; ++mt)
                    ldsm_x4(afH[ks][mt][0], afH[ks][mt][1], afH[ks][mt][2], afH[ks][mt][3],
                            sb + E_Q + abase + mt * 2048 + akb);
            }
        }

        // prefetch next K (overlaps MMA)
        if (job + 1 < je) {
            int nj = job + 1;
            int nib = nj >> 6;
            size_t krow0 = (size_t)(nib >> 6) * S_DIM + (size_t)(nj & 63) * 64;
            u32 nkb = sb + E_K + (buf ^ 1) * 8192;
            #pragma unroll
            for (int l = 0; l < 4; ++l) {
                int row = row16 + 16 * l;
                u32 off = (u32)row * 128 + (u32)lc16 * 16;
                u32 swo = off ^ ((off >> 3) & 0x70);
                cp16(nkb + swo, (const char*)(g_Kh + (krow0 + row) * D_DIM) + lc16 * 16);
            }
            cp_commit();
        }

        // ---- single-pass fp16 MMA, A hoisted ----
        float acc[2][4][4] = {};
        #pragma unroll
        for (int ks = 0; ks < 4; ++ks) {
            const u32 bkb = ((u32)(ks * 32) + bk4) ^ lxor;
            u32 bH[8];
            ldsm_x4(bH[0], bH[1], bH[2], bH[3], kb + bbase4 + bkb);
            ldsm_x4(bH[4], bH[5], bH[6], bH[7], kb + bbase4 + 2048 + bkb);
            #pragma unroll
            for (int mt = 0; mt < 2; ++mt)
                #pragma unroll
                for (int nt = 0; nt < 4; ++nt)
                    mma16816h(acc[mt][nt], afH[ks][mt], bH + nt * 2);
        }

        // ---- epilogue: v * table-rcp(|i-j|), shuffle-packed STG.128 ----
        const int iPos0 = (ib & 63) * 64;
        const int jj0 = jt * 64;
        const int g = lid >> 2, tg = lid & 3;
        const int colbase = ((tg & 1) << 3) + ((tg & 2) << 1);  // 0,8,4,12
        float* ob = out + ((size_t)ib * 64) * S_DIM + jj0;
        #pragma unroll
        for (int mt = 0; mt < 2; ++mt) {
            #pragma unroll
            for (int half = 0; half < 2; ++half) {
                int il = wm * 32 + mt * 16 + g + half * 8;
                int ip = iPos0 + il;
                int kbase = 4096 + ip - jj0;
                float* orow = ob + (size_t)il * S_DIM;
                #pragma unroll
                for (int grp = 0; grp < 2; ++grp) {
                    int jl0 = wn * 32 + grp * 16 + tg * 2;
                    float2 rX = g_rcp[kbase - jl0];
                    float2 rY = g_rcp[kbase - jl0 - 8];
                    const int nt0 = grp * 2, nt1 = grp * 2 + 1;
                    float Xx = acc[mt][nt0][half*2+0] * rX.x;
                    float Xy = acc[mt][nt0][half*2+1] * rX.y;
                    float Yx = acc[mt][nt1][half*2+0] * rY.x;
                    float Yy = acc[mt][nt1][half*2+1] * rY.y;
                    float pXx = __shfl_xor_sync(0xffffffffu, Xx, 1);
                    float pXy = __shfl_xor_sync(0xffffffffu, Xy, 1);
                    float pYx = __shfl_xor_sync(0xffffffffu, Yx, 1);
                    float pYy = __shfl_xor_sync(0xffffffffu, Yy, 1);
                    float4 F = (tg & 1) ? make_float4(pYx, pYy, Yx, Yy)
                                        : make_float4(Xx, Xy, pXx, pXy);
                    int col = wn * 32 + grp * 16 + colbase;
                    *(float4*)(orow + col) = F;
                }
            }
        }
    }
}

extern "C" void kernel_launch(void* const* d_in, const int* in_sizes, int n_in,
                              void* d_out, int out_size) {
    const float* feat = (const float*)d_in[0];
    const float* Wq   = (const float*)d_in[1];
    const float* Wk   = (const float*)d_in[2];
    const float* wch  = (const float*)d_in[3];
    const float* bch  = (const float*)d_in[4];
    const float* ls   = (const float*)d_in[5];
    float* out = (float*)d_out;

    cudaFuncSetAttribute(proj_kernel, cudaFuncAttributeMaxDynamicSharedMemorySize, P_SMEM);
    cudaFuncSetAttribute(energy_kernel, cudaFuncAttributeMaxDynamicSharedMemorySize, E_SMEM);

    wsetup_kernel<<<32, 256>>>(Wq, Wk);
    proj_kernel<<<(B_DIM * S_DIM) / 64, 256, P_SMEM>>>(feat, wch, bch, ls);
    energy_kernel<<<EGRID, 128, E_SMEM>>>(out);
}